// round 9
// baseline (speedup 1.0000x reference)
#include <cuda_runtime.h>
#include <cuda_bf16.h>
#include <cuda_fp16.h>
#include <cstdint>

#define S 4096
#define D 512
#define SD (S * D)
#define DD (D * D)
#define PCN 4096  // concatenated projection width (8 * 512)

// ---------------------------------------------------------------------------
// Scratch (__device__ globals; no allocations allowed)
// ---------------------------------------------------------------------------
__device__ __nv_bfloat16 g_Xh[SD], g_Xl[SD];
__device__ __nv_bfloat16 g_WTc_h[8 * DD], g_WTc_l[8 * DD];  // [4096 n][512 k]
__device__ __nv_bfloat16 g_WTv_h[DD], g_WTv_l[DD];          // [512 n][512 k]
__device__ __half g_Pc_h[(size_t)S * PCN], g_Pc_l[(size_t)S * PCN];
__device__ __half g_VTh[SD], g_VTl[SD];                     // [512 n][4096 k]
__device__ float g_S4[4 * (size_t)S * S];
__device__ __half g_Wh[(size_t)S * S];

// ---------------------------------------------------------------------------
// PTX helpers (baseline PTX only; legal on compute_103)
// ---------------------------------------------------------------------------
__device__ __forceinline__ uint32_t smem_u32(const void* p) {
    uint32_t a;
    asm("{ .reg .u64 t; cvta.to.shared.u64 t, %1; cvt.u32.u64 %0, t; }"
        : "=r"(a) : "l"(p));
    return a;
}

#define CP_ASYNC16(dst, src) \
    asm volatile("cp.async.cg.shared.global [%0], [%1], 16;" :: "r"(dst), "l"(src))
#define CP_COMMIT() asm volatile("cp.async.commit_group;" ::: "memory")
#define CP_WAIT1()  asm volatile("cp.async.wait_group 1;" ::: "memory")

__device__ __forceinline__ void ldsm4(uint32_t* r, uint32_t addr) {
    asm volatile("ldmatrix.sync.aligned.m8n8.x4.shared.b16 {%0,%1,%2,%3}, [%4];"
                 : "=r"(r[0]), "=r"(r[1]), "=r"(r[2]), "=r"(r[3]) : "r"(addr));
}

__device__ __forceinline__ void mma_bf16(float* c, const uint32_t* a,
                                         const uint32_t* b) {
    asm volatile(
        "mma.sync.aligned.m16n8k16.row.col.f32.bf16.bf16.f32 "
        "{%0,%1,%2,%3}, {%4,%5,%6,%7}, {%8,%9}, {%0,%1,%2,%3};"
        : "+f"(c[0]), "+f"(c[1]), "+f"(c[2]), "+f"(c[3])
        : "r"(a[0]), "r"(a[1]), "r"(a[2]), "r"(a[3]), "r"(b[0]), "r"(b[1]));
}

__device__ __forceinline__ void mma_f16(float* c, const uint32_t* a,
                                        const uint32_t* b) {
    asm volatile(
        "mma.sync.aligned.m16n8k16.row.col.f32.f16.f16.f32 "
        "{%0,%1,%2,%3}, {%4,%5,%6,%7}, {%8,%9}, {%0,%1,%2,%3};"
        : "+f"(c[0]), "+f"(c[1]), "+f"(c[2]), "+f"(c[3])
        : "r"(a[0]), "r"(a[1]), "r"(a[2]), "r"(a[3]), "r"(b[0]), "r"(b[1]));
}

// swizzled offset within a tile of 64B rows (4 x 16B slots per row)
__device__ __forceinline__ uint32_t swz(int r, int c16) {
    return (uint32_t)(r * 64 + ((c16 ^ ((r >> 1) & 3)) << 4));
}

// ===========================================================================
// KERNEL 1: 3-pass bf16 GEMM for projections (emits fp16 hi/lo planes).
// CTA 128(M) x 64(N), 8 warps (32x32), K-chunk 32, 3-stage cp.async, 2 CTA/SM.
//   C = Ah@Bh^T + Ah@Bl^T + Al@Bh^T  (A,B K-major bf16)
// MODE_SPLIT: fp16 h/l row-major.  MODE_SPLIT_T: fp16 h/l transposed.
// ===========================================================================
enum { MODE_SPLIT = 1, MODE_SPLIT_T = 2 };

constexpr int A_TILE_B = 8192;    // 128 rows x 64B
constexpr int B_TILE_B = 4096;    // 64 rows x 64B
constexpr int STAGE_B = 2 * A_TILE_B + 2 * B_TILE_B;  // 24KB
constexpr int OFF_AH = 0;
constexpr int OFF_AL = A_TILE_B;
constexpr int OFF_BH = 2 * A_TILE_B;
constexpr int OFF_BL = 2 * A_TILE_B + B_TILE_B;
constexpr int SMEM3_SZ = 3 * STAGE_B;  // 72KB

__device__ __forceinline__ void cp_chunk3(
    uint32_t sbase, int st, const __nv_bfloat16* A0, const __nv_bfloat16* A1,
    const __nv_bfloat16* B0, const __nv_bfloat16* B1, int lda, int ldb,
    int kk, int t) {
    const uint32_t stb = sbase + st * STAGE_B;
#pragma unroll
    for (int i = 0; i < 2; i++) {
        int e = t + i * 256;
        int r = e >> 2, c16 = e & 3;
        uint32_t o = swz(r, c16);
        const char* ga = (const char*)(A0 + (size_t)r * lda + kk) + c16 * 16;
        const char* gb = (const char*)(A1 + (size_t)r * lda + kk) + c16 * 16;
        CP_ASYNC16(stb + OFF_AH + o, ga);
        CP_ASYNC16(stb + OFF_AL + o, gb);
    }
    {
        int r = t >> 2, c16 = t & 3;
        uint32_t o = swz(r, c16);
        const char* ga = (const char*)(B0 + (size_t)r * ldb + kk) + c16 * 16;
        const char* gb = (const char*)(B1 + (size_t)r * ldb + kk) + c16 * 16;
        CP_ASYNC16(stb + OFF_BH + o, ga);
        CP_ASYNC16(stb + OFF_BL + o, gb);
    }
    CP_COMMIT();
}

template <int MODE>
__global__ void __launch_bounds__(256, 2)
gemm3_bf16(const __nv_bfloat16* __restrict__ Ah, const __nv_bfloat16* __restrict__ Al,
           const __nv_bfloat16* __restrict__ Bh, const __nv_bfloat16* __restrict__ Bl,
           __half* __restrict__ Ch, __half* __restrict__ Cl,
           int Mtot, int Ntot, int K, int lda, int ldb) {
    extern __shared__ char sm[];
    const uint32_t sbase = smem_u32(sm);
    const int t = threadIdx.x, lid = t & 31, wid = t >> 5;
    const int wm = wid & 3, wn = wid >> 2;
    const int m0 = blockIdx.y * 128, n0 = blockIdx.x * 64;

    const __nv_bfloat16* A0 = Ah + (size_t)m0 * lda;
    const __nv_bfloat16* A1 = Al + (size_t)m0 * lda;
    const __nv_bfloat16* B0 = Bh + (size_t)n0 * ldb;
    const __nv_bfloat16* B1 = Bl + (size_t)n0 * ldb;

    float acc[2][4][4];
#pragma unroll
    for (int i = 0; i < 2; i++)
#pragma unroll
        for (int j = 0; j < 4; j++)
#pragma unroll
            for (int k = 0; k < 4; k++) acc[i][j][k] = 0.0f;

    const int NCH = K >> 5;
    const int a_row = lid & 15;
    const int a_chi = lid >> 4;
    const int b_row = (lid & 7) + ((lid >> 4) << 3);
    const int b_chi = (lid >> 3) & 1;

    cp_chunk3(sbase, 0, A0, A1, B0, B1, lda, ldb, 0, t);
    cp_chunk3(sbase, 1, A0, A1, B0, B1, lda, ldb, 32, t);

    for (int c = 0; c < NCH; c++) {
        CP_WAIT1();
        __syncthreads();
        if (c + 2 < NCH)
            cp_chunk3(sbase, (c + 2) % 3, A0, A1, B0, B1, lda, ldb, (c + 2) * 32, t);
        else
            CP_COMMIT();

        const uint32_t base = sbase + (c % 3) * STAGE_B;
#pragma unroll
        for (int q = 0; q < 2; q++) {
            uint32_t ahf[2][4], alf[2][4], bhf[4][2], blf[4][2];
#pragma unroll
            for (int am = 0; am < 2; am++) {
                int r = wm * 32 + am * 16 + a_row;
                uint32_t off = swz(r, q * 2 + a_chi);
                ldsm4(ahf[am], base + OFF_AH + off);
                ldsm4(alf[am], base + OFF_AL + off);
            }
#pragma unroll
            for (int g2 = 0; g2 < 2; g2++) {
                int r = wn * 32 + g2 * 16 + b_row;
                uint32_t off = swz(r, q * 2 + b_chi);
                uint32_t rh[4], rl[4];
                ldsm4(rh, base + OFF_BH + off);
                ldsm4(rl, base + OFF_BL + off);
                bhf[2 * g2 + 0][0] = rh[0]; bhf[2 * g2 + 0][1] = rh[1];
                bhf[2 * g2 + 1][0] = rh[2]; bhf[2 * g2 + 1][1] = rh[3];
                blf[2 * g2 + 0][0] = rl[0]; blf[2 * g2 + 0][1] = rl[1];
                blf[2 * g2 + 1][0] = rl[2]; blf[2 * g2 + 1][1] = rl[3];
            }
#pragma unroll
            for (int am = 0; am < 2; am++)
#pragma unroll
                for (int an = 0; an < 4; an++)
                    mma_bf16(acc[am][an], ahf[am], bhf[an]);
#pragma unroll
            for (int am = 0; am < 2; am++)
#pragma unroll
                for (int an = 0; an < 4; an++)
                    mma_bf16(acc[am][an], ahf[am], blf[an]);
#pragma unroll
            for (int am = 0; am < 2; am++)
#pragma unroll
                for (int an = 0; an < 4; an++)
                    mma_bf16(acc[am][an], alf[am], bhf[an]);
        }
    }

    const int t4 = lid >> 2;
    const int n2 = (lid & 3) * 2;
#pragma unroll
    for (int am = 0; am < 2; am++) {
#pragma unroll
        for (int an = 0; an < 4; an++) {
            int m_lo = m0 + wm * 32 + am * 16 + t4;
            int n = n0 + wn * 32 + an * 8 + n2;
            float* a4 = acc[am][an];
            if (MODE == MODE_SPLIT) {
#pragma unroll
                for (int h2 = 0; h2 < 2; h2++) {
                    int m = m_lo + 8 * h2;
                    float v0 = a4[2 * h2], v1 = a4[2 * h2 + 1];
                    __half h0 = __float2half_rn(v0);
                    __half h1 = __float2half_rn(v1);
                    __half2 hh; hh.x = h0; hh.y = h1;
                    __half2 ll;
                    ll.x = __float2half_rn(v0 - __half2float(h0));
                    ll.y = __float2half_rn(v1 - __half2float(h1));
                    *(__half2*)(Ch + (size_t)m * Ntot + n) = hh;
                    *(__half2*)(Cl + (size_t)m * Ntot + n) = ll;
                }
            } else {  // MODE_SPLIT_T
#pragma unroll
                for (int h2 = 0; h2 < 2; h2++) {
                    int m = m_lo + 8 * h2;
#pragma unroll
                    for (int e = 0; e < 2; e++) {
                        float v = a4[2 * h2 + e];
                        __half h = __float2half_rn(v);
                        Ch[(size_t)(n + e) * Mtot + m] = h;
                        Cl[(size_t)(n + e) * Mtot + m] =
                            __float2half_rn(v - __half2float(h));
                    }
                }
            }
        }
    }
}

// ===========================================================================
// KERNEL 2: 2-pass fp16 GEMM (scores + final):  C = A@Bh^T + A@Bl^T, fp32 out
// A is fp16-rounded (single plane); B split into fp16 hi/lo.
// CTA 128x64, 8 warps (32x32), K-chunk 32, 3-stage; 16KB/stage.
// ===========================================================================
constexpr int STAGE2_B = A_TILE_B + 2 * B_TILE_B;  // 16KB: A, Bh, Bl
constexpr int OFF2_A = 0;
constexpr int OFF2_BH = A_TILE_B;
constexpr int OFF2_BL = A_TILE_B + B_TILE_B;
constexpr int SMEM2_SZ = 3 * STAGE2_B;  // 48KB

__device__ __forceinline__ void cp_chunk2(
    uint32_t sbase, int st, const __half* A0, const __half* B0, const __half* B1,
    int lda, int ldb, int kk, int t) {
    const uint32_t stb = sbase + st * STAGE2_B;
#pragma unroll
    for (int i = 0; i < 2; i++) {
        int e = t + i * 256;
        int r = e >> 2, c16 = e & 3;
        uint32_t o = swz(r, c16);
        CP_ASYNC16(stb + OFF2_A + o,
                   (const char*)(A0 + (size_t)r * lda + kk) + c16 * 16);
    }
    {
        int r = t >> 2, c16 = t & 3;
        uint32_t o = swz(r, c16);
        CP_ASYNC16(stb + OFF2_BH + o,
                   (const char*)(B0 + (size_t)r * ldb + kk) + c16 * 16);
        CP_ASYNC16(stb + OFF2_BL + o,
                   (const char*)(B1 + (size_t)r * ldb + kk) + c16 * 16);
    }
    CP_COMMIT();
}

__global__ void __launch_bounds__(256, 2)
gemm2_f16(const __half* __restrict__ A, const __half* __restrict__ Bh,
          const __half* __restrict__ Bl, float* __restrict__ C,
          int Mtot, int Ntot, int K, int lda, int ldb,
          int azoff, int bzoff, long long czoff) {
    extern __shared__ char sm[];
    const uint32_t sbase = smem_u32(sm);
    const int t = threadIdx.x, lid = t & 31, wid = t >> 5;
    const int wm = wid & 3, wn = wid >> 2;
    const int m0 = blockIdx.y * 128, n0 = blockIdx.x * 64;
    const size_t z = blockIdx.z;

    const __half* A0 = A + (size_t)m0 * lda + z * azoff;
    const __half* B0 = Bh + (size_t)n0 * ldb + z * bzoff;
    const __half* B1 = Bl + (size_t)n0 * ldb + z * bzoff;
    C += z * czoff;

    float acc[2][4][4];
#pragma unroll
    for (int i = 0; i < 2; i++)
#pragma unroll
        for (int j = 0; j < 4; j++)
#pragma unroll
            for (int k = 0; k < 4; k++) acc[i][j][k] = 0.0f;

    const int NCH = K >> 5;
    const int a_row = lid & 15;
    const int a_chi = lid >> 4;
    const int b_row = (lid & 7) + ((lid >> 4) << 3);
    const int b_chi = (lid >> 3) & 1;

    cp_chunk2(sbase, 0, A0, B0, B1, lda, ldb, 0, t);
    cp_chunk2(sbase, 1, A0, B0, B1, lda, ldb, 32, t);

    for (int c = 0; c < NCH; c++) {
        CP_WAIT1();
        __syncthreads();
        if (c + 2 < NCH)
            cp_chunk2(sbase, (c + 2) % 3, A0, B0, B1, lda, ldb, (c + 2) * 32, t);
        else
            CP_COMMIT();

        const uint32_t base = sbase + (c % 3) * STAGE2_B;
#pragma unroll
        for (int q = 0; q < 2; q++) {
            uint32_t af[2][4], bhf[4][2], blf[4][2];
#pragma unroll
            for (int am = 0; am < 2; am++) {
                int r = wm * 32 + am * 16 + a_row;
                ldsm4(af[am], base + OFF2_A + swz(r, q * 2 + a_chi));
            }
#pragma unroll
            for (int g2 = 0; g2 < 2; g2++) {
                int r = wn * 32 + g2 * 16 + b_row;
                uint32_t off = swz(r, q * 2 + b_chi);
                uint32_t rh[4], rl[4];
                ldsm4(rh, base + OFF2_BH + off);
                ldsm4(rl, base + OFF2_BL + off);
                bhf[2 * g2 + 0][0] = rh[0]; bhf[2 * g2 + 0][1] = rh[1];
                bhf[2 * g2 + 1][0] = rh[2]; bhf[2 * g2 + 1][1] = rh[3];
                blf[2 * g2 + 0][0] = rl[0]; blf[2 * g2 + 0][1] = rl[1];
                blf[2 * g2 + 1][0] = rl[2]; blf[2 * g2 + 1][1] = rl[3];
            }
#pragma unroll
            for (int am = 0; am < 2; am++)
#pragma unroll
                for (int an = 0; an < 4; an++)
                    mma_f16(acc[am][an], af[am], bhf[an]);
#pragma unroll
            for (int am = 0; am < 2; am++)
#pragma unroll
                for (int an = 0; an < 4; an++)
                    mma_f16(acc[am][an], af[am], blf[an]);
        }
    }

    const int t4 = lid >> 2;
    const int n2 = (lid & 3) * 2;
#pragma unroll
    for (int am = 0; am < 2; am++) {
#pragma unroll
        for (int an = 0; an < 4; an++) {
            int m_lo = m0 + wm * 32 + am * 16 + t4;
            int n = n0 + wn * 32 + an * 8 + n2;
            float* a4 = acc[am][an];
            __stcs((float2*)(C + (size_t)m_lo * Ntot + n),
                   make_float2(a4[0], a4[1]));
            __stcs((float2*)(C + (size_t)(m_lo + 8) * Ntot + n),
                   make_float2(a4[2], a4[3]));
        }
    }
}

// ---------------------------------------------------------------------------
// splits (x and weights -> bf16 hi/lo, transposed for weights)
// ---------------------------------------------------------------------------
__global__ void split_x(const float* __restrict__ x, __nv_bfloat16* __restrict__ xh,
                        __nv_bfloat16* __restrict__ xl) {
    int i = blockIdx.x * 256 + threadIdx.x;
    float v = x[i];
    __nv_bfloat16 h = __float2bfloat16(v);
    xh[i] = h;
    xl[i] = __float2bfloat16(v - __bfloat162float(h));
}

struct W9 { const float* p[9]; };

__global__ void splitT_all(W9 w9, __nv_bfloat16* __restrict__ WTc_h,
                           __nv_bfloat16* __restrict__ WTc_l,
                           __nv_bfloat16* __restrict__ WTv_h,
                           __nv_bfloat16* __restrict__ WTv_l) {
    __shared__ float tile[32][33];
    const int tx = threadIdx.x, ty = threadIdx.y;
    const int kt = blockIdx.x * 32, nt = blockIdx.y * 32;
    const int wi = blockIdx.z;
    const float* w = w9.p[wi];
#pragma unroll
    for (int j = 0; j < 4; j++) {
        int r = ty + 8 * j;
        tile[r][tx] = w[(size_t)(kt + r) * D + nt + tx];
    }
    __syncthreads();
#pragma unroll
    for (int j = 0; j < 4; j++) {
        int n_loc = ty + 8 * j;
        float v = tile[tx][n_loc];
        __nv_bfloat16 h = __float2bfloat16(v);
        __nv_bfloat16 l = __float2bfloat16(v - __bfloat162float(h));
        if (wi < 8) {
            size_t o = (size_t)(wi * 512 + nt + n_loc) * D + kt + tx;
            WTc_h[o] = h;
            WTc_l[o] = l;
        } else {
            size_t o = (size_t)(nt + n_loc) * D + kt + tx;
            WTv_h[o] = h;
            WTv_l[o] = l;
        }
    }
}

// ---------------------------------------------------------------------------
// warp-shuffle block helpers (256 threads, 8 warps)
// ---------------------------------------------------------------------------
__device__ __forceinline__ float wmax(float v) {
#pragma unroll
    for (int o = 16; o; o >>= 1) v = fmaxf(v, __shfl_xor_sync(0xffffffffu, v, o));
    return v;
}
__device__ __forceinline__ float blockMax8(float v, float* sw, int w, int l) {
    v = wmax(v);
    if (l == 0) sw[w] = v;
    __syncthreads();
    float r = sw[0];
#pragma unroll
    for (int k = 1; k < 8; k++) r = fmaxf(r, sw[k]);
    __syncthreads();
    return r;
}
__device__ __forceinline__ float blockSum8(float v, float* sw, int w, int l) {
#pragma unroll
    for (int o = 16; o; o >>= 1) v += __shfl_xor_sync(0xffffffffu, v, o);
    if (l == 0) sw[w] = v;
    __syncthreads();
    float r = 0.0f;
#pragma unroll
    for (int k = 0; k < 8; k++) r += sw[k];
    __syncthreads();
    return r;
}
__device__ __forceinline__ float blockScanExcl(float s, float* sw, int w, int l,
                                               float* tot) {
    float incl = s;
#pragma unroll
    for (int o = 1; o < 32; o <<= 1) {
        float x = __shfl_up_sync(0xffffffffu, incl, o);
        if (l >= o) incl += x;
    }
    if (l == 31) sw[w] = incl;
    __syncthreads();
    float woff = 0.0f, tt = 0.0f;
#pragma unroll
    for (int k = 0; k < 8; k++) {
        float sv = sw[k];
        tt += sv;
        if (k < w) woff += sv;
    }
    __syncthreads();
    *tot = tt;
    return incl - s + woff;
}

// ---------------------------------------------------------------------------
// Fused per-row pipeline (emits fp32 att_weight + fp16 plane for final GEMM)
// ---------------------------------------------------------------------------
__global__ __launch_bounds__(256) void row_fused(float* __restrict__ Wout) {
    __shared__ float sw[8];
    const int i = blockIdx.x;
    const int t = threadIdx.x;
    const int w = t >> 5, l = t & 31;
    const int j0 = t * 16;
    const float inv_norm = 0.04419417382415922f;  // 1/sqrt(512)

    const float* Sl = g_S4 + 0 * (size_t)S * S + (size_t)i * S;
    const float* Sr = g_S4 + 1 * (size_t)S * S + (size_t)i * S;
    const float* Sg = g_S4 + 2 * (size_t)S * S + (size_t)i * S;
    const float* Sp = g_S4 + 3 * (size_t)S * S + (size_t)i * S;

    float lcdf[16], rcdf[16];

    {  // left boundary
        float e[16];
        float m = -1e30f;
#pragma unroll
        for (int u4 = 0; u4 < 4; u4++) {
            float4 v = __ldcs(reinterpret_cast<const float4*>(Sl + j0 + 4 * u4));
            e[4 * u4 + 0] = v.x; e[4 * u4 + 1] = v.y;
            e[4 * u4 + 2] = v.z; e[4 * u4 + 3] = v.w;
        }
#pragma unroll
        for (int u = 0; u < 16; u++) {
            int j = j0 + u;
            float s = (j <= i) ? e[u] * inv_norm : -1e30f;
            e[u] = s;
            m = fmaxf(m, s);
        }
        m = blockMax8(m, sw, w, l);
        float lsum = 0.0f;
#pragma unroll
        for (int u = 0; u < 16; u++) {
            int j = j0 + u;
            float ev = (j <= i) ? __expf(e[u] - m) : 0.0f;
            e[u] = ev;
            lsum += ev;
        }
        float tot;
        float off = blockScanExcl(lsum, sw, w, l, &tot);
        float inv = 1.0f / tot;
        float c = 0.0f;
#pragma unroll
        for (int u = 0; u < 16; u++) {
            c += e[u];
            lcdf[u] = (c + off) * inv;
        }
    }

    {  // right boundary
        float e[16];
        float m = -1e30f;
#pragma unroll
        for (int u4 = 0; u4 < 4; u4++) {
            float4 v = __ldcs(reinterpret_cast<const float4*>(Sr + j0 + 4 * u4));
            e[4 * u4 + 0] = v.x; e[4 * u4 + 1] = v.y;
            e[4 * u4 + 2] = v.z; e[4 * u4 + 3] = v.w;
        }
#pragma unroll
        for (int u = 0; u < 16; u++) {
            int j = j0 + u;
            float s = (j >= i) ? e[u] * inv_norm : -1e30f;
            e[u] = s;
            m = fmaxf(m, s);
        }
        m = blockMax8(m, sw, w, l);
        float rsum = 0.0f;
#pragma unroll
        for (int u = 0; u < 16; u++) {
            int j = j0 + u;
            float ev = (j >= i) ? __expf(e[u] - m) : 0.0f;
            e[u] = ev;
            rsum += ev;
        }
        float tot;
        float excl = blockScanExcl(rsum, sw, w, l, &tot);
        float suff = tot - excl - rsum;
        float inv = 1.0f / tot;
        float c = 0.0f;
#pragma unroll
        for (int u = 15; u >= 0; u--) {
            c += e[u];
            rcdf[u] = (c + suff) * inv;
        }
    }

    {  // combine + final softmax
        float wv[16], p[16];
#pragma unroll
        for (int u4 = 0; u4 < 4; u4++) {
            float4 vg = __ldcs(reinterpret_cast<const float4*>(Sg + j0 + 4 * u4));
            float4 vp = __ldcs(reinterpret_cast<const float4*>(Sp + j0 + 4 * u4));
            wv[4 * u4 + 0] = vg.x; wv[4 * u4 + 1] = vg.y;
            wv[4 * u4 + 2] = vg.z; wv[4 * u4 + 3] = vg.w;
            p[4 * u4 + 0] = vp.x; p[4 * u4 + 1] = vp.y;
            p[4 * u4 + 2] = vp.z; p[4 * u4 + 3] = vp.w;
        }
        float m = -1e30f;
#pragma unroll
        for (int u = 0; u < 16; u++) {
            float sc = (wv[u] + p[u] * lcdf[u] * rcdf[u]) * inv_norm;
            wv[u] = sc;
            m = fmaxf(m, sc);
        }
        m = blockMax8(m, sw, w, l);
        float lsum = 0.0f;
#pragma unroll
        for (int u = 0; u < 16; u++) {
            float ev = __expf(wv[u] - m);
            wv[u] = ev;
            lsum += ev;
        }
        float tot = blockSum8(lsum, sw, w, l);
        float inv = 1.0f / tot;
        float* Wrow = Wout + (size_t)i * S + j0;
        __half* Hrow = g_Wh + (size_t)i * S + j0;
#pragma unroll
        for (int u4 = 0; u4 < 4; u4++) {
            float4 o;
            o.x = wv[4 * u4 + 0] * inv;
            o.y = wv[4 * u4 + 1] * inv;
            o.z = wv[4 * u4 + 2] * inv;
            o.w = wv[4 * u4 + 3] * inv;
            *reinterpret_cast<float4*>(Wrow + 4 * u4) = o;
            __half2 h01, h23;
            h01.x = __float2half_rn(o.x); h01.y = __float2half_rn(o.y);
            h23.x = __float2half_rn(o.z); h23.y = __float2half_rn(o.w);
            *(__half2*)(Hrow + 4 * u4 + 0) = h01;
            *(__half2*)(Hrow + 4 * u4 + 2) = h23;
        }
    }
}

// ---------------------------------------------------------------------------
// Launch. inputs: x, w_ql, w_kl, w_qr, w_kr, w_qg, w_kg, w_qloc, w_kloc, w_v
// Output layout: [att_output (S*D) | att_weight (S*S)]
// ---------------------------------------------------------------------------
extern "C" void kernel_launch(void* const* d_in, const int* in_sizes, int n_in,
                              void* d_out, int out_size) {
    const float* x = (const float*)d_in[0];
    W9 w9;
    for (int i = 0; i < 9; i++) w9.p[i] = (const float*)d_in[1 + i];

    float* out = (float*)d_out;
    float* Wout = out + SD;

    __nv_bfloat16 *Xh, *Xl, *WTc_h, *WTc_l, *WTv_h, *WTv_l;
    __half *Pc_h, *Pc_l, *VTh, *VTl, *Wh;
    float* S4;
    cudaGetSymbolAddress((void**)&Xh, g_Xh);
    cudaGetSymbolAddress((void**)&Xl, g_Xl);
    cudaGetSymbolAddress((void**)&WTc_h, g_WTc_h);
    cudaGetSymbolAddress((void**)&WTc_l, g_WTc_l);
    cudaGetSymbolAddress((void**)&WTv_h, g_WTv_h);
    cudaGetSymbolAddress((void**)&WTv_l, g_WTv_l);
    cudaGetSymbolAddress((void**)&Pc_h, g_Pc_h);
    cudaGetSymbolAddress((void**)&Pc_l, g_Pc_l);
    cudaGetSymbolAddress((void**)&VTh, g_VTh);
    cudaGetSymbolAddress((void**)&VTl, g_VTl);
    cudaGetSymbolAddress((void**)&S4, g_S4);
    cudaGetSymbolAddress((void**)&Wh, g_Wh);

    cudaFuncSetAttribute(gemm3_bf16<MODE_SPLIT>,
                         cudaFuncAttributeMaxDynamicSharedMemorySize, SMEM3_SZ);
    cudaFuncSetAttribute(gemm3_bf16<MODE_SPLIT_T>,
                         cudaFuncAttributeMaxDynamicSharedMemorySize, SMEM3_SZ);
    cudaFuncSetAttribute(gemm2_f16,
                         cudaFuncAttributeMaxDynamicSharedMemorySize, SMEM2_SZ);

    // 1) splits
    split_x<<<SD / 256, 256>>>(x, Xh, Xl);
    dim3 tb(32, 8);
    dim3 tg(D / 32, D / 32, 9);
    splitT_all<<<tg, tb>>>(w9, WTc_h, WTc_l, WTv_h, WTv_l);

    // 2) projections (bf16x3 -> fp16 hi/lo planes)
    dim3 gp(PCN / 64, S / 128, 1);
    gemm3_bf16<MODE_SPLIT><<<gp, 256, SMEM3_SZ>>>(
        Xh, Xl, WTc_h, WTc_l, Pc_h, Pc_l, S, PCN, D, D, D);

    dim3 gv(D / 64, S / 128, 1);
    gemm3_bf16<MODE_SPLIT_T><<<gv, 256, SMEM3_SZ>>>(
        Xh, Xl, WTv_h, WTv_l, VTh, VTl, S, D, D, D, D);

    // 3) four S x S score matrices, fp16 2-pass, one batched launch
    //    A = q block (fp16 plane), B = k block (fp16 hi/lo)
    dim3 gs(S / 64, S / 128, 4);
    gemm2_f16<<<gs, 256, SMEM2_SZ>>>(
        Pc_h, Pc_h + 512, Pc_l + 512, S4,
        S, S, D, PCN, PCN, 1024, 1024, (long long)S * S);

    // 4) fused boundary softmaxes + cumsums + combine + final softmax
    row_fused<<<S, 256>>>(Wout);

    // 5) att_output = att_weight @ v  (fp16 2-pass)
    dim3 gf(D / 64, S / 128, 1);
    gemm2_f16<<<gf, 256, SMEM2_SZ>>>(
        Wh, VTh, VTl, out, S, D, S, S, S, 0, 0, 0);
}

// round 10
// speedup vs baseline: 1.1822x; 1.1822x over previous
#include <cuda_runtime.h>
#include <cuda_bf16.h>
#include <cstdint>

#define S 4096
#define D 512
#define SD (S * D)
#define DD (D * D)
#define PCN 4096  // concatenated projection width (8 * 512)

// ---------------------------------------------------------------------------
// Scratch (__device__ globals; no allocations allowed)
// ---------------------------------------------------------------------------
__device__ __nv_bfloat16 g_Xh[SD], g_Xl[SD];
__device__ __nv_bfloat16 g_WTc_h[8 * DD], g_WTc_l[8 * DD];  // [4096 n][512 k]
__device__ __nv_bfloat16 g_WTv_h[DD], g_WTv_l[DD];          // [512 n][512 k]
__device__ __nv_bfloat16 g_Pc_h[(size_t)S * PCN], g_Pc_l[(size_t)S * PCN];
__device__ __nv_bfloat16 g_VTh[SD], g_VTl[SD];              // [512 n][4096 k]
__device__ float g_S4[4 * (size_t)S * S];
__device__ __nv_bfloat16 g_Wh[(size_t)S * S], g_Wl[(size_t)S * S];

// ---------------------------------------------------------------------------
// PTX helpers (baseline PTX only; legal on compute_103)
// ---------------------------------------------------------------------------
__device__ __forceinline__ uint32_t smem_u32(const void* p) {
    uint32_t a;
    asm("{ .reg .u64 t; cvta.to.shared.u64 t, %1; cvt.u32.u64 %0, t; }"
        : "=r"(a) : "l"(p));
    return a;
}

#define CP_ASYNC16(dst, src) \
    asm volatile("cp.async.cg.shared.global [%0], [%1], 16;" :: "r"(dst), "l"(src))
#define CP_COMMIT() asm volatile("cp.async.commit_group;" ::: "memory")
#define CP_WAIT1()  asm volatile("cp.async.wait_group 1;" ::: "memory")

__device__ __forceinline__ void ldsm4(uint32_t* r, uint32_t addr) {
    asm volatile("ldmatrix.sync.aligned.m8n8.x4.shared.b16 {%0,%1,%2,%3}, [%4];"
                 : "=r"(r[0]), "=r"(r[1]), "=r"(r[2]), "=r"(r[3]) : "r"(addr));
}

__device__ __forceinline__ void mma16816(float* c, const uint32_t* a,
                                         const uint32_t* b) {
    asm volatile(
        "mma.sync.aligned.m16n8k16.row.col.f32.bf16.bf16.f32 "
        "{%0,%1,%2,%3}, {%4,%5,%6,%7}, {%8,%9}, {%0,%1,%2,%3};"
        : "+f"(c[0]), "+f"(c[1]), "+f"(c[2]), "+f"(c[3])
        : "r"(a[0]), "r"(a[1]), "r"(a[2]), "r"(a[3]), "r"(b[0]), "r"(b[1]));
}

// swizzled offset within a tile of 64B rows (4 x 16B slots per row)
__device__ __forceinline__ uint32_t swz(int r, int c16) {
    return (uint32_t)(r * 64 + ((c16 ^ ((r >> 1) & 3)) << 4));
}

// ---------------------------------------------------------------------------
// HMMA bf16x3 GEMM:  C[M,N] = Ah@Bh^T + Ah@Bl^T + Al@Bh^T   (A,B K-major)
// CTA tile 128(M) x 64(N), 8 warps (warp tile 32x32), K-chunk 32, 3-stage
// cp.async pipeline; 2 CTAs resident / SM.
// tri=1: z==0 keeps only lower-triangle blocks (n0 <= m0+127),
//        z==1 keeps only upper-triangle blocks (n0+63 >= m0).
// ---------------------------------------------------------------------------
enum { MODE_F32 = 0, MODE_SPLIT = 1, MODE_SPLIT_T = 2 };

constexpr int A_TILE_B = 8192;    // 128 rows x 64B
constexpr int B_TILE_B = 4096;    // 64 rows x 64B
constexpr int STAGE_B = 2 * A_TILE_B + 2 * B_TILE_B;  // 24KB: Ah, Al, Bh, Bl
constexpr int OFF_AH = 0;
constexpr int OFF_AL = A_TILE_B;
constexpr int OFF_BH = 2 * A_TILE_B;
constexpr int OFF_BL = 2 * A_TILE_B + B_TILE_B;
constexpr int SMEM_SZ = 3 * STAGE_B;  // 72KB

__device__ __forceinline__ void cp_chunk(
    uint32_t sbase, int st, const __nv_bfloat16* A0, const __nv_bfloat16* A1,
    const __nv_bfloat16* B0, const __nv_bfloat16* B1, int lda, int ldb,
    int kk, int t) {
    const uint32_t stb = sbase + st * STAGE_B;
#pragma unroll
    for (int i = 0; i < 2; i++) {
        int e = t + i * 256;
        int r = e >> 2, c16 = e & 3;
        uint32_t o = swz(r, c16);
        const char* ga = (const char*)(A0 + (size_t)r * lda + kk) + c16 * 16;
        const char* gb = (const char*)(A1 + (size_t)r * lda + kk) + c16 * 16;
        CP_ASYNC16(stb + OFF_AH + o, ga);
        CP_ASYNC16(stb + OFF_AL + o, gb);
    }
    {
        int r = t >> 2, c16 = t & 3;
        uint32_t o = swz(r, c16);
        const char* ga = (const char*)(B0 + (size_t)r * ldb + kk) + c16 * 16;
        const char* gb = (const char*)(B1 + (size_t)r * ldb + kk) + c16 * 16;
        CP_ASYNC16(stb + OFF_BH + o, ga);
        CP_ASYNC16(stb + OFF_BL + o, gb);
    }
    CP_COMMIT();
}

template <int MODE>
__global__ void __launch_bounds__(256, 2)
gemm_hmma(const __nv_bfloat16* __restrict__ Ah, const __nv_bfloat16* __restrict__ Al,
          const __nv_bfloat16* __restrict__ Bh, const __nv_bfloat16* __restrict__ Bl,
          float* __restrict__ C, __nv_bfloat16* __restrict__ Ch,
          __nv_bfloat16* __restrict__ Cl, int Mtot, int Ntot, int K,
          int lda, int ldb, int azoff, int bzoff, long long czoff, int tri) {
    const int m0 = blockIdx.y * 128, n0 = blockIdx.x * 64;
    const size_t z = blockIdx.z;

    if (tri) {
        if (z == 0 && n0 > m0 + 127) return;       // Sl: lower triangle only
        if (z == 1 && n0 + 63 < m0) return;        // Sr: upper triangle only
    }

    extern __shared__ char sm[];
    const uint32_t sbase = smem_u32(sm);
    const int t = threadIdx.x, lid = t & 31, wid = t >> 5;
    const int wm = wid & 3, wn = wid >> 2;           // 4 x 2 warp grid

    const __nv_bfloat16* A0 = Ah + (size_t)m0 * lda + z * azoff;
    const __nv_bfloat16* A1 = Al + (size_t)m0 * lda + z * azoff;
    const __nv_bfloat16* B0 = Bh + (size_t)n0 * ldb + z * bzoff;
    const __nv_bfloat16* B1 = Bl + (size_t)n0 * ldb + z * bzoff;
    C += z * czoff;

    float acc[2][4][4];
#pragma unroll
    for (int i = 0; i < 2; i++)
#pragma unroll
        for (int j = 0; j < 4; j++)
#pragma unroll
            for (int k = 0; k < 4; k++) acc[i][j][k] = 0.0f;

    const int NCH = K >> 5;  // 32-wide chunks

    // ldmatrix lane coords
    const int a_row = lid & 15;
    const int a_chi = lid >> 4;
    const int b_row = (lid & 7) + ((lid >> 4) << 3);
    const int b_chi = (lid >> 3) & 1;

    cp_chunk(sbase, 0, A0, A1, B0, B1, lda, ldb, 0, t);
    cp_chunk(sbase, 1, A0, A1, B0, B1, lda, ldb, 32, t);

    for (int c = 0; c < NCH; c++) {
        CP_WAIT1();
        __syncthreads();
        if (c + 2 < NCH)
            cp_chunk(sbase, (c + 2) % 3, A0, A1, B0, B1, lda, ldb, (c + 2) * 32, t);
        else
            CP_COMMIT();  // keep group count so WAIT1 drains chunk c+1

        const uint32_t base = sbase + (c % 3) * STAGE_B;
#pragma unroll
        for (int q = 0; q < 2; q++) {
            uint32_t ahf[2][4], alf[2][4], bhf[2][2], blf[2][2];
#pragma unroll
            for (int am = 0; am < 2; am++) {
                int r = wm * 32 + am * 16 + a_row;
                uint32_t off = swz(r, q * 2 + a_chi);
                ldsm4(ahf[am], base + OFF_AH + off);
                ldsm4(alf[am], base + OFF_AL + off);
            }
            {
                int r = wn * 32 + b_row;          // n 0..15
                uint32_t off = swz(r, q * 2 + b_chi);
                uint32_t rh[4], rl[4];
                ldsm4(rh, base + OFF_BH + off);
                ldsm4(rl, base + OFF_BL + off);
                bhf[0][0] = rh[0]; bhf[0][1] = rh[1];
                bhf[1][0] = rh[2]; bhf[1][1] = rh[3];
                blf[0][0] = rl[0]; blf[0][1] = rl[1];
                blf[1][0] = rl[2]; blf[1][1] = rl[3];
            }
            uint32_t bhf2[2][2], blf2[2][2];
            {
                int r = wn * 32 + 16 + b_row;     // n 16..31
                uint32_t off = swz(r, q * 2 + b_chi);
                uint32_t rh[4], rl[4];
                ldsm4(rh, base + OFF_BH + off);
                ldsm4(rl, base + OFF_BL + off);
                bhf2[0][0] = rh[0]; bhf2[0][1] = rh[1];
                bhf2[1][0] = rh[2]; bhf2[1][1] = rh[3];
                blf2[0][0] = rl[0]; blf2[0][1] = rl[1];
                blf2[1][0] = rl[2]; blf2[1][1] = rl[3];
            }
#pragma unroll
            for (int am = 0; am < 2; am++) {
                mma16816(acc[am][0], ahf[am], bhf[0]);
                mma16816(acc[am][1], ahf[am], bhf[1]);
                mma16816(acc[am][2], ahf[am], bhf2[0]);
                mma16816(acc[am][3], ahf[am], bhf2[1]);
            }
#pragma unroll
            for (int am = 0; am < 2; am++) {
                mma16816(acc[am][0], ahf[am], blf[0]);
                mma16816(acc[am][1], ahf[am], blf[1]);
                mma16816(acc[am][2], ahf[am], blf2[0]);
                mma16816(acc[am][3], ahf[am], blf2[1]);
            }
#pragma unroll
            for (int am = 0; am < 2; am++) {
                mma16816(acc[am][0], alf[am], bhf[0]);
                mma16816(acc[am][1], alf[am], bhf[1]);
                mma16816(acc[am][2], alf[am], bhf2[0]);
                mma16816(acc[am][3], alf[am], bhf2[1]);
            }
        }
    }

    // epilogue
    const int t4 = lid >> 2;
    const int n2 = (lid & 3) * 2;
#pragma unroll
    for (int am = 0; am < 2; am++) {
#pragma unroll
        for (int an = 0; an < 4; an++) {
            int m_lo = m0 + wm * 32 + am * 16 + t4;
            int n = n0 + wn * 32 + an * 8 + n2;
            float* a4 = acc[am][an];
            if (MODE == MODE_F32) {
                __stcs((float2*)(C + (size_t)m_lo * Ntot + n),
                       make_float2(a4[0], a4[1]));
                __stcs((float2*)(C + (size_t)(m_lo + 8) * Ntot + n),
                       make_float2(a4[2], a4[3]));
            } else if (MODE == MODE_SPLIT) {
#pragma unroll
                for (int h2 = 0; h2 < 2; h2++) {
                    int m = m_lo + 8 * h2;
                    float v0 = a4[2 * h2], v1 = a4[2 * h2 + 1];
                    __nv_bfloat16 h0 = __float2bfloat16(v0);
                    __nv_bfloat16 h1 = __float2bfloat16(v1);
                    __nv_bfloat162 hh; hh.x = h0; hh.y = h1;
                    __nv_bfloat162 ll;
                    ll.x = __float2bfloat16(v0 - __bfloat162float(h0));
                    ll.y = __float2bfloat16(v1 - __bfloat162float(h1));
                    *(__nv_bfloat162*)(Ch + (size_t)m * Ntot + n) = hh;
                    *(__nv_bfloat162*)(Cl + (size_t)m * Ntot + n) = ll;
                }
            } else {  // MODE_SPLIT_T
#pragma unroll
                for (int h2 = 0; h2 < 2; h2++) {
                    int m = m_lo + 8 * h2;
#pragma unroll
                    for (int e = 0; e < 2; e++) {
                        float v = a4[2 * h2 + e];
                        __nv_bfloat16 h = __float2bfloat16(v);
                        Ch[(size_t)(n + e) * Mtot + m] = h;
                        Cl[(size_t)(n + e) * Mtot + m] =
                            __float2bfloat16(v - __bfloat162float(h));
                    }
                }
            }
        }
    }
}

// ---------------------------------------------------------------------------
// splits
// ---------------------------------------------------------------------------
__global__ void split_x(const float* __restrict__ x, __nv_bfloat16* __restrict__ xh,
                        __nv_bfloat16* __restrict__ xl) {
    int i = blockIdx.x * 256 + threadIdx.x;
    float v = x[i];
    __nv_bfloat16 h = __float2bfloat16(v);
    xh[i] = h;
    xl[i] = __float2bfloat16(v - __bfloat162float(h));
}

struct W9 { const float* p[9]; };

// transpose + split all 9 weights; one launch, coalesced via shared tile
__global__ void splitT_all(W9 w9, __nv_bfloat16* __restrict__ WTc_h,
                           __nv_bfloat16* __restrict__ WTc_l,
                           __nv_bfloat16* __restrict__ WTv_h,
                           __nv_bfloat16* __restrict__ WTv_l) {
    __shared__ float tile[32][33];
    const int tx = threadIdx.x, ty = threadIdx.y;
    const int kt = blockIdx.x * 32, nt = blockIdx.y * 32;
    const int wi = blockIdx.z;
    const float* w = w9.p[wi];
#pragma unroll
    for (int j = 0; j < 4; j++) {
        int r = ty + 8 * j;
        tile[r][tx] = w[(size_t)(kt + r) * D + nt + tx];
    }
    __syncthreads();
#pragma unroll
    for (int j = 0; j < 4; j++) {
        int n_loc = ty + 8 * j;
        float v = tile[tx][n_loc];
        __nv_bfloat16 h = __float2bfloat16(v);
        __nv_bfloat16 l = __float2bfloat16(v - __bfloat162float(h));
        if (wi < 8) {
            size_t o = (size_t)(wi * 512 + nt + n_loc) * D + kt + tx;
            WTc_h[o] = h;
            WTc_l[o] = l;
        } else {
            size_t o = (size_t)(nt + n_loc) * D + kt + tx;
            WTv_h[o] = h;
            WTv_l[o] = l;
        }
    }
}

// ---------------------------------------------------------------------------
// warp-shuffle block helpers (256 threads, 8 warps)
// ---------------------------------------------------------------------------
__device__ __forceinline__ float wmax(float v) {
#pragma unroll
    for (int o = 16; o; o >>= 1) v = fmaxf(v, __shfl_xor_sync(0xffffffffu, v, o));
    return v;
}
__device__ __forceinline__ float blockMax8(float v, float* sw, int w, int l) {
    v = wmax(v);
    if (l == 0) sw[w] = v;
    __syncthreads();
    float r = sw[0];
#pragma unroll
    for (int k = 1; k < 8; k++) r = fmaxf(r, sw[k]);
    __syncthreads();
    return r;
}
__device__ __forceinline__ float blockSum8(float v, float* sw, int w, int l) {
#pragma unroll
    for (int o = 16; o; o >>= 1) v += __shfl_xor_sync(0xffffffffu, v, o);
    if (l == 0) sw[w] = v;
    __syncthreads();
    float r = 0.0f;
#pragma unroll
    for (int k = 0; k < 8; k++) r += sw[k];
    __syncthreads();
    return r;
}
// returns EXCLUSIVE prefix of s across the block; *tot = block total
__device__ __forceinline__ float blockScanExcl(float s, float* sw, int w, int l,
                                               float* tot) {
    float incl = s;
#pragma unroll
    for (int o = 1; o < 32; o <<= 1) {
        float x = __shfl_up_sync(0xffffffffu, incl, o);
        if (l >= o) incl += x;
    }
    if (l == 31) sw[w] = incl;
    __syncthreads();
    float woff = 0.0f, tt = 0.0f;
#pragma unroll
    for (int k = 0; k < 8; k++) {
        float sv = sw[k];
        tt += sv;
        if (k < w) woff += sv;
    }
    __syncthreads();
    *tot = tt;
    return incl - s + woff;
}

// ---------------------------------------------------------------------------
// Fused per-row pipeline (also emits bf16 hi/lo of att_weight).
// Sl is only read where the chunk may contain j <= i; Sr where j >= i.
// ---------------------------------------------------------------------------
__global__ __launch_bounds__(256) void row_fused(float* __restrict__ Wout) {
    __shared__ float sw[8];
    const int i = blockIdx.x;
    const int t = threadIdx.x;
    const int w = t >> 5, l = t & 31;
    const int j0 = t * 16;
    const float inv_norm = 0.04419417382415922f;  // 1/sqrt(512)

    const float* Sl = g_S4 + 0 * (size_t)S * S + (size_t)i * S;
    const float* Sr = g_S4 + 1 * (size_t)S * S + (size_t)i * S;
    const float* Sg = g_S4 + 2 * (size_t)S * S + (size_t)i * S;
    const float* Sp = g_S4 + 3 * (size_t)S * S + (size_t)i * S;

    float lcdf[16], rcdf[16];

    {  // left boundary (uses only j <= i)
        float e[16];
        float m = -1e30f;
        float lsum = 0.0f;
        if (j0 <= i) {
#pragma unroll
            for (int u4 = 0; u4 < 4; u4++) {
                float4 v = __ldcs(reinterpret_cast<const float4*>(Sl + j0 + 4 * u4));
                e[4 * u4 + 0] = v.x; e[4 * u4 + 1] = v.y;
                e[4 * u4 + 2] = v.z; e[4 * u4 + 3] = v.w;
            }
#pragma unroll
            for (int u = 0; u < 16; u++) {
                int j = j0 + u;
                float s = (j <= i) ? e[u] * inv_norm : -1e30f;
                e[u] = s;
                m = fmaxf(m, s);
            }
        } else {
#pragma unroll
            for (int u = 0; u < 16; u++) e[u] = -1e30f;
        }
        m = blockMax8(m, sw, w, l);
        if (j0 <= i) {
#pragma unroll
            for (int u = 0; u < 16; u++) {
                int j = j0 + u;
                float ev = (j <= i) ? __expf(e[u] - m) : 0.0f;
                e[u] = ev;
                lsum += ev;
            }
        } else {
#pragma unroll
            for (int u = 0; u < 16; u++) e[u] = 0.0f;
        }
        float tot;
        float off = blockScanExcl(lsum, sw, w, l, &tot);
        float inv = 1.0f / tot;
        float c = 0.0f;
#pragma unroll
        for (int u = 0; u < 16; u++) {
            c += e[u];
            lcdf[u] = (c + off) * inv;
        }
    }

    {  // right boundary (uses only j >= i)
        float e[16];
        float m = -1e30f;
        float rsum = 0.0f;
        if (j0 + 15 >= i) {
#pragma unroll
            for (int u4 = 0; u4 < 4; u4++) {
                float4 v = __ldcs(reinterpret_cast<const float4*>(Sr + j0 + 4 * u4));
                e[4 * u4 + 0] = v.x; e[4 * u4 + 1] = v.y;
                e[4 * u4 + 2] = v.z; e[4 * u4 + 3] = v.w;
            }
#pragma unroll
            for (int u = 0; u < 16; u++) {
                int j = j0 + u;
                float s = (j >= i) ? e[u] * inv_norm : -1e30f;
                e[u] = s;
                m = fmaxf(m, s);
            }
        } else {
#pragma unroll
            for (int u = 0; u < 16; u++) e[u] = -1e30f;
        }
        m = blockMax8(m, sw, w, l);
        if (j0 + 15 >= i) {
#pragma unroll
            for (int u = 0; u < 16; u++) {
                int j = j0 + u;
                float ev = (j >= i) ? __expf(e[u] - m) : 0.0f;
                e[u] = ev;
                rsum += ev;
            }
        } else {
#pragma unroll
            for (int u = 0; u < 16; u++) e[u] = 0.0f;
        }
        float tot;
        float excl = blockScanExcl(rsum, sw, w, l, &tot);
        float suff = tot - excl - rsum;
        float inv = 1.0f / tot;
        float c = 0.0f;
#pragma unroll
        for (int u = 15; u >= 0; u--) {
            c += e[u];
            rcdf[u] = (c + suff) * inv;
        }
    }

    {  // combine + final softmax
        float wv[16], p[16];
#pragma unroll
        for (int u4 = 0; u4 < 4; u4++) {
            float4 vg = __ldcs(reinterpret_cast<const float4*>(Sg + j0 + 4 * u4));
            float4 vp = __ldcs(reinterpret_cast<const float4*>(Sp + j0 + 4 * u4));
            wv[4 * u4 + 0] = vg.x; wv[4 * u4 + 1] = vg.y;
            wv[4 * u4 + 2] = vg.z; wv[4 * u4 + 3] = vg.w;
            p[4 * u4 + 0] = vp.x; p[4 * u4 + 1] = vp.y;
            p[4 * u4 + 2] = vp.z; p[4 * u4 + 3] = vp.w;
        }
        float m = -1e30f;
#pragma unroll
        for (int u = 0; u < 16; u++) {
            float sc = (wv[u] + p[u] * lcdf[u] * rcdf[u]) * inv_norm;
            wv[u] = sc;
            m = fmaxf(m, sc);
        }
        m = blockMax8(m, sw, w, l);
        float lsum = 0.0f;
#pragma unroll
        for (int u = 0; u < 16; u++) {
            float ev = __expf(wv[u] - m);
            wv[u] = ev;
            lsum += ev;
        }
        float tot = blockSum8(lsum, sw, w, l);
        float inv = 1.0f / tot;
        float* Wrow = Wout + (size_t)i * S + j0;
        __nv_bfloat16* Hrow = g_Wh + (size_t)i * S + j0;
        __nv_bfloat16* Lrow = g_Wl + (size_t)i * S + j0;
#pragma unroll
        for (int u4 = 0; u4 < 4; u4++) {
            float4 o;
            o.x = wv[4 * u4 + 0] * inv;
            o.y = wv[4 * u4 + 1] * inv;
            o.z = wv[4 * u4 + 2] * inv;
            o.w = wv[4 * u4 + 3] * inv;
            *reinterpret_cast<float4*>(Wrow + 4 * u4) = o;
            float vv[4] = {o.x, o.y, o.z, o.w};
#pragma unroll
            for (int u = 0; u < 4; u++) {
                __nv_bfloat16 h = __float2bfloat16(vv[u]);
                Hrow[4 * u4 + u] = h;
                Lrow[4 * u4 + u] = __float2bfloat16(vv[u] - __bfloat162float(h));
            }
        }
    }
}

// ---------------------------------------------------------------------------
// Launch. inputs: x, w_ql, w_kl, w_qr, w_kr, w_qg, w_kg, w_qloc, w_kloc, w_v
// Output layout: [att_output (S*D) | att_weight (S*S)]
// ---------------------------------------------------------------------------
extern "C" void kernel_launch(void* const* d_in, const int* in_sizes, int n_in,
                              void* d_out, int out_size) {
    const float* x = (const float*)d_in[0];
    W9 w9;
    for (int i = 0; i < 9; i++) w9.p[i] = (const float*)d_in[1 + i];

    float* out = (float*)d_out;
    float* Wout = out + SD;

    __nv_bfloat16 *Xh, *Xl, *WTc_h, *WTc_l, *WTv_h, *WTv_l;
    __nv_bfloat16 *Pc_h, *Pc_l, *VTh, *VTl, *Wh, *Wl;
    float* S4;
    cudaGetSymbolAddress((void**)&Xh, g_Xh);
    cudaGetSymbolAddress((void**)&Xl, g_Xl);
    cudaGetSymbolAddress((void**)&WTc_h, g_WTc_h);
    cudaGetSymbolAddress((void**)&WTc_l, g_WTc_l);
    cudaGetSymbolAddress((void**)&WTv_h, g_WTv_h);
    cudaGetSymbolAddress((void**)&WTv_l, g_WTv_l);
    cudaGetSymbolAddress((void**)&Pc_h, g_Pc_h);
    cudaGetSymbolAddress((void**)&Pc_l, g_Pc_l);
    cudaGetSymbolAddress((void**)&VTh, g_VTh);
    cudaGetSymbolAddress((void**)&VTl, g_VTl);
    cudaGetSymbolAddress((void**)&S4, g_S4);
    cudaGetSymbolAddress((void**)&Wh, g_Wh);
    cudaGetSymbolAddress((void**)&Wl, g_Wl);

    cudaFuncSetAttribute(gemm_hmma<MODE_F32>,
                         cudaFuncAttributeMaxDynamicSharedMemorySize, SMEM_SZ);
    cudaFuncSetAttribute(gemm_hmma<MODE_SPLIT>,
                         cudaFuncAttributeMaxDynamicSharedMemorySize, SMEM_SZ);
    cudaFuncSetAttribute(gemm_hmma<MODE_SPLIT_T>,
                         cudaFuncAttributeMaxDynamicSharedMemorySize, SMEM_SZ);

    // 1) splits: x elementwise, weights transposed (one launch each)
    split_x<<<SD / 256, 256>>>(x, Xh, Xl);
    dim3 tb(32, 8);
    dim3 tg(D / 32, D / 32, 9);
    splitT_all<<<tg, tb>>>(w9, WTc_h, WTc_l, WTv_h, WTv_l);

    // 2) fused projections: Pcat[4096, 4096] = x @ [w_ql|w_kl|...|w_kloc]
    dim3 gp(PCN / 64, S / 128, 1);
    gemm_hmma<MODE_SPLIT><<<gp, 256, SMEM_SZ>>>(
        Xh, Xl, WTc_h, WTc_l, nullptr, Pc_h, Pc_l,
        S, PCN, D, D, D, 0, 0, 0, 0);

    //    v projection, written transposed: VT[512, 4096]
    dim3 gv(D / 64, S / 128, 1);
    gemm_hmma<MODE_SPLIT_T><<<gv, 256, SMEM_SZ>>>(
        Xh, Xl, WTv_h, WTv_l, nullptr, VTh, VTl,
        S, D, D, D, D, 0, 0, 0, 0);

    // 3) four S x S score matrices in ONE batched launch (z = 0..3);
    //    z=0 (Sl) lower-triangle blocks only, z=1 (Sr) upper-triangle only.
    dim3 gs(S / 64, S / 128, 4);
    gemm_hmma<MODE_F32><<<gs, 256, SMEM_SZ>>>(
        Pc_h, Pc_l, Pc_h + 512, Pc_l + 512, S4, nullptr, nullptr,
        S, S, D, PCN, PCN, 1024, 1024, (long long)S * S, 1);

    // 4) fused boundary softmaxes + cumsums + combine + final softmax
    row_fused<<<S, 256>>>(Wout);

    // 5) att_output = att_weight @ v   (W bf16x3  x  V^T bf16x3)
    dim3 gf(D / 64, S / 128, 1);
    gemm_hmma<MODE_F32><<<gf, 256, SMEM_SZ>>>(
        Wh, Wl, VTh, VTl, out, nullptr, nullptr,
        S, D, S, S, S, 0, 0, 0, 0);
}

// round 14
// speedup vs baseline: 1.2166x; 1.0291x over previous
#include <cuda_runtime.h>
#include <cuda_bf16.h>
#include <cstdint>

#define S 4096
#define D 512
#define SD (S * D)
#define DD (D * D)
#define PCN 4096  // concatenated projection width (8 * 512)

// ---------------------------------------------------------------------------
// Scratch (__device__ globals; no allocations allowed)
// ---------------------------------------------------------------------------
__device__ __nv_bfloat16 g_Xh[SD], g_Xl[SD];
__device__ __nv_bfloat16 g_WTc_h[8 * DD], g_WTc_l[8 * DD];  // [4096 n][512 k]
__device__ __nv_bfloat16 g_WTv_h[DD], g_WTv_l[DD];          // [512 n][512 k]
__device__ __nv_bfloat16 g_Pc_h[(size_t)S * PCN], g_Pc_l[(size_t)S * PCN];
__device__ __nv_bfloat16 g_VTh[SD], g_VTl[SD];              // [512 n][4096 k]
__device__ float g_S4[4 * (size_t)S * S];
__device__ __nv_bfloat16 g_Wh[(size_t)S * S], g_Wl[(size_t)S * S];

// ---------------------------------------------------------------------------
// PTX helpers (baseline PTX only; legal on compute_103)
// ---------------------------------------------------------------------------
__device__ __forceinline__ uint32_t smem_u32(const void* p) {
    uint32_t a;
    asm("{ .reg .u64 t; cvta.to.shared.u64 t, %1; cvt.u32.u64 %0, t; }"
        : "=r"(a) : "l"(p));
    return a;
}

#define CP_ASYNC16(dst, src) \
    asm volatile("cp.async.cg.shared.global [%0], [%1], 16;" :: "r"(dst), "l"(src))
#define CP_COMMIT() asm volatile("cp.async.commit_group;" ::: "memory")
#define CP_WAIT1()  asm volatile("cp.async.wait_group 1;" ::: "memory")

__device__ __forceinline__ void ldsm4(uint32_t* r, uint32_t addr) {
    asm volatile("ldmatrix.sync.aligned.m8n8.x4.shared.b16 {%0,%1,%2,%3}, [%4];"
                 : "=r"(r[0]), "=r"(r[1]), "=r"(r[2]), "=r"(r[3]) : "r"(addr));
}

__device__ __forceinline__ void mma16816(float* c, const uint32_t* a,
                                         const uint32_t* b) {
    asm volatile(
        "mma.sync.aligned.m16n8k16.row.col.f32.bf16.bf16.f32 "
        "{%0,%1,%2,%3}, {%4,%5,%6,%7}, {%8,%9}, {%0,%1,%2,%3};"
        : "+f"(c[0]), "+f"(c[1]), "+f"(c[2]), "+f"(c[3])
        : "r"(a[0]), "r"(a[1]), "r"(a[2]), "r"(a[3]), "r"(b[0]), "r"(b[1]));
}

// swizzled offset within a tile of 64B rows (4 x 16B slots per row)
__device__ __forceinline__ uint32_t swz(int r, int c16) {
    return (uint32_t)(r * 64 + ((c16 ^ ((r >> 1) & 3)) << 4));
}

// ---------------------------------------------------------------------------
// HMMA bf16x3 GEMM:  C[M,N] = Ah@Bh^T + Ah@Bl^T + Al@Bh^T   (A,B K-major)
// CTA tile 64(M) x 64(N), 4 warps (2x2, warp tile 32x32), K-chunk 32,
// 3-stage cp.async; 16KB/stage, 48KB total => 4 CTAs resident / SM.
// tri=1: z==0 keeps only n0 <= m0+63; z==1 keeps only n0+63 >= m0.
// ---------------------------------------------------------------------------
enum { MODE_F32 = 0, MODE_SPLIT = 1, MODE_SPLIT_T = 2 };

constexpr int A_TILE_B = 4096;    // 64 rows x 64B
constexpr int B_TILE_B = 4096;    // 64 rows x 64B
constexpr int STAGE_B = 2 * A_TILE_B + 2 * B_TILE_B;  // 16KB: Ah, Al, Bh, Bl
constexpr int OFF_AH = 0;
constexpr int OFF_AL = A_TILE_B;
constexpr int OFF_BH = 2 * A_TILE_B;
constexpr int OFF_BL = 2 * A_TILE_B + B_TILE_B;
constexpr int SMEM_SZ = 3 * STAGE_B;  // 48KB

__device__ __forceinline__ void cp_chunk(
    uint32_t sbase, int st, const __nv_bfloat16* A0, const __nv_bfloat16* A1,
    const __nv_bfloat16* B0, const __nv_bfloat16* B1, int lda, int ldb,
    int kk, int t) {
    const uint32_t stb = sbase + st * STAGE_B;
    // each tile: 64 rows x 4 slots = 256 16B ops; 128 threads -> 2 per tile
#pragma unroll
    for (int i = 0; i < 2; i++) {
        int e = t + i * 128;
        int r = e >> 2, c16 = e & 3;
        uint32_t o = swz(r, c16);
        CP_ASYNC16(stb + OFF_AH + o,
                   (const char*)(A0 + (size_t)r * lda + kk) + c16 * 16);
        CP_ASYNC16(stb + OFF_AL + o,
                   (const char*)(A1 + (size_t)r * lda + kk) + c16 * 16);
        CP_ASYNC16(stb + OFF_BH + o,
                   (const char*)(B0 + (size_t)r * ldb + kk) + c16 * 16);
        CP_ASYNC16(stb + OFF_BL + o,
                   (const char*)(B1 + (size_t)r * ldb + kk) + c16 * 16);
    }
    CP_COMMIT();
}

template <int MODE>
__global__ void __launch_bounds__(128, 4)
gemm_hmma(const __nv_bfloat16* __restrict__ Ah, const __nv_bfloat16* __restrict__ Al,
          const __nv_bfloat16* __restrict__ Bh, const __nv_bfloat16* __restrict__ Bl,
          float* __restrict__ C, __nv_bfloat16* __restrict__ Ch,
          __nv_bfloat16* __restrict__ Cl, int Mtot, int Ntot, int K,
          int lda, int ldb, int azoff, int bzoff, long long czoff, int tri) {
    const int m0 = blockIdx.y * 64, n0 = blockIdx.x * 64;
    const size_t z = blockIdx.z;

    if (tri) {
        if (z == 0 && n0 > m0 + 63) return;        // Sl: lower triangle only
        if (z == 1 && n0 + 63 < m0) return;        // Sr: upper triangle only
    }

    extern __shared__ char sm[];
    const uint32_t sbase = smem_u32(sm);
    const int t = threadIdx.x, lid = t & 31, wid = t >> 5;
    const int wm = wid & 1, wn = wid >> 1;           // 2 x 2 warp grid

    const __nv_bfloat16* A0 = Ah + (size_t)m0 * lda + z * azoff;
    const __nv_bfloat16* A1 = Al + (size_t)m0 * lda + z * azoff;
    const __nv_bfloat16* B0 = Bh + (size_t)n0 * ldb + z * bzoff;
    const __nv_bfloat16* B1 = Bl + (size_t)n0 * ldb + z * bzoff;
    C += z * czoff;

    float acc[2][4][4];
#pragma unroll
    for (int i = 0; i < 2; i++)
#pragma unroll
        for (int j = 0; j < 4; j++)
#pragma unroll
            for (int k = 0; k < 4; k++) acc[i][j][k] = 0.0f;

    const int NCH = K >> 5;  // 32-wide chunks

    // ldmatrix lane coords
    const int a_row = lid & 15;
    const int a_chi = lid >> 4;
    const int b_row = (lid & 7) + ((lid >> 4) << 3);
    const int b_chi = (lid >> 3) & 1;

    cp_chunk(sbase, 0, A0, A1, B0, B1, lda, ldb, 0, t);
    cp_chunk(sbase, 1, A0, A1, B0, B1, lda, ldb, 32, t);

    for (int c = 0; c < NCH; c++) {
        CP_WAIT1();
        __syncthreads();
        if (c + 2 < NCH)
            cp_chunk(sbase, (c + 2) % 3, A0, A1, B0, B1, lda, ldb, (c + 2) * 32, t);
        else
            CP_COMMIT();  // keep group count so WAIT1 drains chunk c+1

        const uint32_t base = sbase + (c % 3) * STAGE_B;
#pragma unroll
        for (int q = 0; q < 2; q++) {
            uint32_t ahf[2][4], alf[2][4], bhf[2][2], blf[2][2];
#pragma unroll
            for (int am = 0; am < 2; am++) {
                int r = wm * 32 + am * 16 + a_row;
                uint32_t off = swz(r, q * 2 + a_chi);
                ldsm4(ahf[am], base + OFF_AH + off);
                ldsm4(alf[am], base + OFF_AL + off);
            }
            {
                int r = wn * 32 + b_row;          // n 0..15
                uint32_t off = swz(r, q * 2 + b_chi);
                uint32_t rh[4], rl[4];
                ldsm4(rh, base + OFF_BH + off);
                ldsm4(rl, base + OFF_BL + off);
                bhf[0][0] = rh[0]; bhf[0][1] = rh[1];
                bhf[1][0] = rh[2]; bhf[1][1] = rh[3];
                blf[0][0] = rl[0]; blf[0][1] = rl[1];
                blf[1][0] = rl[2]; blf[1][1] = rl[3];
            }
            uint32_t bhf2[2][2], blf2[2][2];
            {
                int r = wn * 32 + 16 + b_row;     // n 16..31
                uint32_t off = swz(r, q * 2 + b_chi);
                uint32_t rh[4], rl[4];
                ldsm4(rh, base + OFF_BH + off);
                ldsm4(rl, base + OFF_BL + off);
                bhf2[0][0] = rh[0]; bhf2[0][1] = rh[1];
                bhf2[1][0] = rh[2]; bhf2[1][1] = rh[3];
                blf2[0][0] = rl[0]; blf2[0][1] = rl[1];
                blf2[1][0] = rl[2]; blf2[1][1] = rl[3];
            }
#pragma unroll
            for (int am = 0; am < 2; am++) {
                mma16816(acc[am][0], ahf[am], bhf[0]);
                mma16816(acc[am][1], ahf[am], bhf[1]);
                mma16816(acc[am][2], ahf[am], bhf2[0]);
                mma16816(acc[am][3], ahf[am], bhf2[1]);
            }
#pragma unroll
            for (int am = 0; am < 2; am++) {
                mma16816(acc[am][0], ahf[am], blf[0]);
                mma16816(acc[am][1], ahf[am], blf[1]);
                mma16816(acc[am][2], ahf[am], blf2[0]);
                mma16816(acc[am][3], ahf[am], blf2[1]);
            }
#pragma unroll
            for (int am = 0; am < 2; am++) {
                mma16816(acc[am][0], alf[am], bhf[0]);
                mma16816(acc[am][1], alf[am], bhf[1]);
                mma16816(acc[am][2], alf[am], bhf2[0]);
                mma16816(acc[am][3], alf[am], bhf2[1]);
            }
        }
    }

    // epilogue
    const int t4 = lid >> 2;
    const int n2 = (lid & 3) * 2;
#pragma unroll
    for (int am = 0; am < 2; am++) {
#pragma unroll
        for (int an = 0; an < 4; an++) {
            int m_lo = m0 + wm * 32 + am * 16 + t4;
            int n = n0 + wn * 32 + an * 8 + n2;
            float* a4 = acc[am][an];
            if (MODE == MODE_F32) {
                __stcs((float2*)(C + (size_t)m_lo * Ntot + n),
                       make_float2(a4[0], a4[1]));
                __stcs((float2*)(C + (size_t)(m_lo + 8) * Ntot + n),
                       make_float2(a4[2], a4[3]));
            } else if (MODE == MODE_SPLIT) {
#pragma unroll
                for (int h2 = 0; h2 < 2; h2++) {
                    int m = m_lo + 8 * h2;
                    float v0 = a4[2 * h2], v1 = a4[2 * h2 + 1];
                    __nv_bfloat16 h0 = __float2bfloat16(v0);
                    __nv_bfloat16 h1 = __float2bfloat16(v1);
                    __nv_bfloat162 hh; hh.x = h0; hh.y = h1;
                    __nv_bfloat162 ll;
                    ll.x = __float2bfloat16(v0 - __bfloat162float(h0));
                    ll.y = __float2bfloat16(v1 - __bfloat162float(h1));
                    *(__nv_bfloat162*)(Ch + (size_t)m * Ntot + n) = hh;
                    *(__nv_bfloat162*)(Cl + (size_t)m * Ntot + n) = ll;
                }
            } else {  // MODE_SPLIT_T
#pragma unroll
                for (int h2 = 0; h2 < 2; h2++) {
                    int m = m_lo + 8 * h2;
#pragma unroll
                    for (int e = 0; e < 2; e++) {
                        float v = a4[2 * h2 + e];
                        __nv_bfloat16 h = __float2bfloat16(v);
                        Ch[(size_t)(n + e) * Mtot + m] = h;
                        Cl[(size_t)(n + e) * Mtot + m] =
                            __float2bfloat16(v - __bfloat162float(h));
                    }
                }
            }
        }
    }
}

// ---------------------------------------------------------------------------
// splits
// ---------------------------------------------------------------------------
__global__ void split_x(const float* __restrict__ x, __nv_bfloat16* __restrict__ xh,
                        __nv_bfloat16* __restrict__ xl) {
    int i = blockIdx.x * 256 + threadIdx.x;
    float v = x[i];
    __nv_bfloat16 h = __float2bfloat16(v);
    xh[i] = h;
    xl[i] = __float2bfloat16(v - __bfloat162float(h));
}

struct W9 { const float* p[9]; };

// transpose + split all 9 weights; one launch, coalesced via shared tile
__global__ void splitT_all(W9 w9, __nv_bfloat16* __restrict__ WTc_h,
                           __nv_bfloat16* __restrict__ WTc_l,
                           __nv_bfloat16* __restrict__ WTv_h,
                           __nv_bfloat16* __restrict__ WTv_l) {
    __shared__ float tile[32][33];
    const int tx = threadIdx.x, ty = threadIdx.y;
    const int kt = blockIdx.x * 32, nt = blockIdx.y * 32;
    const int wi = blockIdx.z;
    const float* w = w9.p[wi];
#pragma unroll
    for (int j = 0; j < 4; j++) {
        int r = ty + 8 * j;
        tile[r][tx] = w[(size_t)(kt + r) * D + nt + tx];
    }
    __syncthreads();
#pragma unroll
    for (int j = 0; j < 4; j++) {
        int n_loc = ty + 8 * j;
        float v = tile[tx][n_loc];
        __nv_bfloat16 h = __float2bfloat16(v);
        __nv_bfloat16 l = __float2bfloat16(v - __bfloat162float(h));
        if (wi < 8) {
            size_t o = (size_t)(wi * 512 + nt + n_loc) * D + kt + tx;
            WTc_h[o] = h;
            WTc_l[o] = l;
        } else {
            size_t o = (size_t)(nt + n_loc) * D + kt + tx;
            WTv_h[o] = h;
            WTv_l[o] = l;
        }
    }
}

// ---------------------------------------------------------------------------
// warp-shuffle block helpers (256 threads, 8 warps)
// ---------------------------------------------------------------------------
__device__ __forceinline__ float wmax(float v) {
#pragma unroll
    for (int o = 16; o; o >>= 1) v = fmaxf(v, __shfl_xor_sync(0xffffffffu, v, o));
    return v;
}
__device__ __forceinline__ float blockMax8(float v, float* sw, int w, int l) {
    v = wmax(v);
    if (l == 0) sw[w] = v;
    __syncthreads();
    float r = sw[0];
#pragma unroll
    for (int k = 1; k < 8; k++) r = fmaxf(r, sw[k]);
    __syncthreads();
    return r;
}
__device__ __forceinline__ float blockSum8(float v, float* sw, int w, int l) {
#pragma unroll
    for (int o = 16; o; o >>= 1) v += __shfl_xor_sync(0xffffffffu, v, o);
    if (l == 0) sw[w] = v;
    __syncthreads();
    float r = 0.0f;
#pragma unroll
    for (int k = 0; k < 8; k++) r += sw[k];
    __syncthreads();
    return r;
}
// returns EXCLUSIVE prefix of s across the block; *tot = block total
__device__ __forceinline__ float blockScanExcl(float s, float* sw, int w, int l,
                                               float* tot) {
    float incl = s;
#pragma unroll
    for (int o = 1; o < 32; o <<= 1) {
        float x = __shfl_up_sync(0xffffffffu, incl, o);
        if (l >= o) incl += x;
    }
    if (l == 31) sw[w] = incl;
    __syncthreads();
    float woff = 0.0f, tt = 0.0f;
#pragma unroll
    for (int k = 0; k < 8; k++) {
        float sv = sw[k];
        tt += sv;
        if (k < w) woff += sv;
    }
    __syncthreads();
    *tot = tt;
    return incl - s + woff;
}

// ---------------------------------------------------------------------------
// Fused per-row pipeline (also emits bf16 hi/lo of att_weight).
// Sl is only read where the chunk may contain j <= i; Sr where j >= i.
// ---------------------------------------------------------------------------
__global__ __launch_bounds__(256) void row_fused(float* __restrict__ Wout) {
    __shared__ float sw[8];
    const int i = blockIdx.x;
    const int t = threadIdx.x;
    const int w = t >> 5, l = t & 31;
    const int j0 = t * 16;
    const float inv_norm = 0.04419417382415922f;  // 1/sqrt(512)

    const float* Sl = g_S4 + 0 * (size_t)S * S + (size_t)i * S;
    const float* Sr = g_S4 + 1 * (size_t)S * S + (size_t)i * S;
    const float* Sg = g_S4 + 2 * (size_t)S * S + (size_t)i * S;
    const float* Sp = g_S4 + 3 * (size_t)S * S + (size_t)i * S;

    float lcdf[16], rcdf[16];

    {  // left boundary (uses only j <= i)
        float e[16];
        float m = -1e30f;
        float lsum = 0.0f;
        if (j0 <= i) {
#pragma unroll
            for (int u4 = 0; u4 < 4; u4++) {
                float4 v = __ldcs(reinterpret_cast<const float4*>(Sl + j0 + 4 * u4));
                e[4 * u4 + 0] = v.x; e[4 * u4 + 1] = v.y;
                e[4 * u4 + 2] = v.z; e[4 * u4 + 3] = v.w;
            }
#pragma unroll
            for (int u = 0; u < 16; u++) {
                int j = j0 + u;
                float s = (j <= i) ? e[u] * inv_norm : -1e30f;
                e[u] = s;
                m = fmaxf(m, s);
            }
        } else {
#pragma unroll
            for (int u = 0; u < 16; u++) e[u] = -1e30f;
        }
        m = blockMax8(m, sw, w, l);
        if (j0 <= i) {
#pragma unroll
            for (int u = 0; u < 16; u++) {
                int j = j0 + u;
                float ev = (j <= i) ? __expf(e[u] - m) : 0.0f;
                e[u] = ev;
                lsum += ev;
            }
        } else {
#pragma unroll
            for (int u = 0; u < 16; u++) e[u] = 0.0f;
        }
        float tot;
        float off = blockScanExcl(lsum, sw, w, l, &tot);
        float inv = 1.0f / tot;
        float c = 0.0f;
#pragma unroll
        for (int u = 0; u < 16; u++) {
            c += e[u];
            lcdf[u] = (c + off) * inv;
        }
    }

    {  // right boundary (uses only j >= i)
        float e[16];
        float m = -1e30f;
        float rsum = 0.0f;
        if (j0 + 15 >= i) {
#pragma unroll
            for (int u4 = 0; u4 < 4; u4++) {
                float4 v = __ldcs(reinterpret_cast<const float4*>(Sr + j0 + 4 * u4));
                e[4 * u4 + 0] = v.x; e[4 * u4 + 1] = v.y;
                e[4 * u4 + 2] = v.z; e[4 * u4 + 3] = v.w;
            }
#pragma unroll
            for (int u = 0; u < 16; u++) {
                int j = j0 + u;
                float s = (j >= i) ? e[u] * inv_norm : -1e30f;
                e[u] = s;
                m = fmaxf(m, s);
            }
        } else {
#pragma unroll
            for (int u = 0; u < 16; u++) e[u] = -1e30f;
        }
        m = blockMax8(m, sw, w, l);
        if (j0 + 15 >= i) {
#pragma unroll
            for (int u = 0; u < 16; u++) {
                int j = j0 + u;
                float ev = (j >= i) ? __expf(e[u] - m) : 0.0f;
                e[u] = ev;
                rsum += ev;
            }
        } else {
#pragma unroll
            for (int u = 0; u < 16; u++) e[u] = 0.0f;
        }
        float tot;
        float excl = blockScanExcl(rsum, sw, w, l, &tot);
        float suff = tot - excl - rsum;
        float inv = 1.0f / tot;
        float c = 0.0f;
#pragma unroll
        for (int u = 15; u >= 0; u--) {
            c += e[u];
            rcdf[u] = (c + suff) * inv;
        }
    }

    {  // combine + final softmax
        float wv[16], p[16];
#pragma unroll
        for (int u4 = 0; u4 < 4; u4++) {
            float4 vg = __ldcs(reinterpret_cast<const float4*>(Sg + j0 + 4 * u4));
            float4 vp = __ldcs(reinterpret_cast<const float4*>(Sp + j0 + 4 * u4));
            wv[4 * u4 + 0] = vg.x; wv[4 * u4 + 1] = vg.y;
            wv[4 * u4 + 2] = vg.z; wv[4 * u4 + 3] = vg.w;
            p[4 * u4 + 0] = vp.x; p[4 * u4 + 1] = vp.y;
            p[4 * u4 + 2] = vp.z; p[4 * u4 + 3] = vp.w;
        }
        float m = -1e30f;
#pragma unroll
        for (int u = 0; u < 16; u++) {
            float sc = (wv[u] + p[u] * lcdf[u] * rcdf[u]) * inv_norm;
            wv[u] = sc;
            m = fmaxf(m, sc);
        }
        m = blockMax8(m, sw, w, l);
        float lsum = 0.0f;
#pragma unroll
        for (int u = 0; u < 16; u++) {
            float ev = __expf(wv[u] - m);
            wv[u] = ev;
            lsum += ev;
        }
        float tot = blockSum8(lsum, sw, w, l);
        float inv = 1.0f / tot;
        float* Wrow = Wout + (size_t)i * S + j0;
        __nv_bfloat16* Hrow = g_Wh + (size_t)i * S + j0;
        __nv_bfloat16* Lrow = g_Wl + (size_t)i * S + j0;
#pragma unroll
        for (int u4 = 0; u4 < 4; u4++) {
            float4 o;
            o.x = wv[4 * u4 + 0] * inv;
            o.y = wv[4 * u4 + 1] * inv;
            o.z = wv[4 * u4 + 2] * inv;
            o.w = wv[4 * u4 + 3] * inv;
            *reinterpret_cast<float4*>(Wrow + 4 * u4) = o;
            float vv[4] = {o.x, o.y, o.z, o.w};
#pragma unroll
            for (int u = 0; u < 4; u++) {
                __nv_bfloat16 h = __float2bfloat16(vv[u]);
                Hrow[4 * u4 + u] = h;
                Lrow[4 * u4 + u] = __float2bfloat16(vv[u] - __bfloat162float(h));
            }
        }
    }
}

// ---------------------------------------------------------------------------
// Launch. inputs: x, w_ql, w_kl, w_qr, w_kr, w_qg, w_kg, w_qloc, w_kloc, w_v
// Output layout: [att_output (S*D) | att_weight (S*S)]
// ---------------------------------------------------------------------------
extern "C" void kernel_launch(void* const* d_in, const int* in_sizes, int n_in,
                              void* d_out, int out_size) {
    const float* x = (const float*)d_in[0];
    W9 w9;
    for (int i = 0; i < 9; i++) w9.p[i] = (const float*)d_in[1 + i];

    float* out = (float*)d_out;
    float* Wout = out + SD;

    __nv_bfloat16 *Xh, *Xl, *WTc_h, *WTc_l, *WTv_h, *WTv_l;
    __nv_bfloat16 *Pc_h, *Pc_l, *VTh, *VTl, *Wh, *Wl;
    float* S4;
    cudaGetSymbolAddress((void**)&Xh, g_Xh);
    cudaGetSymbolAddress((void**)&Xl, g_Xl);
    cudaGetSymbolAddress((void**)&WTc_h, g_WTc_h);
    cudaGetSymbolAddress((void**)&WTc_l, g_WTc_l);
    cudaGetSymbolAddress((void**)&WTv_h, g_WTv_h);
    cudaGetSymbolAddress((void**)&WTv_l, g_WTv_l);
    cudaGetSymbolAddress((void**)&Pc_h, g_Pc_h);
    cudaGetSymbolAddress((void**)&Pc_l, g_Pc_l);
    cudaGetSymbolAddress((void**)&VTh, g_VTh);
    cudaGetSymbolAddress((void**)&VTl, g_VTl);
    cudaGetSymbolAddress((void**)&S4, g_S4);
    cudaGetSymbolAddress((void**)&Wh, g_Wh);
    cudaGetSymbolAddress((void**)&Wl, g_Wl);

    cudaFuncSetAttribute(gemm_hmma<MODE_F32>,
                         cudaFuncAttributeMaxDynamicSharedMemorySize, SMEM_SZ);
    cudaFuncSetAttribute(gemm_hmma<MODE_SPLIT>,
                         cudaFuncAttributeMaxDynamicSharedMemorySize, SMEM_SZ);
    cudaFuncSetAttribute(gemm_hmma<MODE_SPLIT_T>,
                         cudaFuncAttributeMaxDynamicSharedMemorySize, SMEM_SZ);

    // 1) splits: x elementwise, weights transposed (one launch each)
    split_x<<<SD / 256, 256>>>(x, Xh, Xl);
    dim3 tb(32, 8);
    dim3 tg(D / 32, D / 32, 9);
    splitT_all<<<tg, tb>>>(w9, WTc_h, WTc_l, WTv_h, WTv_l);

    // 2) fused projections: Pcat[4096, 4096] = x @ [w_ql|w_kl|...|w_kloc]
    dim3 gp(PCN / 64, S / 64, 1);
    gemm_hmma<MODE_SPLIT><<<gp, 128, SMEM_SZ>>>(
        Xh, Xl, WTc_h, WTc_l, nullptr, Pc_h, Pc_l,
        S, PCN, D, D, D, 0, 0, 0, 0);

    //    v projection, written transposed: VT[512, 4096]
    dim3 gv(D / 64, S / 64, 1);
    gemm_hmma<MODE_SPLIT_T><<<gv, 128, SMEM_SZ>>>(
        Xh, Xl, WTv_h, WTv_l, nullptr, VTh, VTl,
        S, D, D, D, D, 0, 0, 0, 0);

    // 3) four S x S score matrices in ONE batched launch (z = 0..3);
    //    z=0 (Sl) lower-triangle blocks only, z=1 (Sr) upper-triangle only.
    dim3 gs(S / 64, S / 64, 4);
    gemm_hmma<MODE_F32><<<gs, 128, SMEM_SZ>>>(
        Pc_h, Pc_l, Pc_h + 512, Pc_l + 512, S4, nullptr, nullptr,
        S, S, D, PCN, PCN, 1024, 1024, (long long)S * S, 1);

    // 4) fused boundary softmaxes + cumsums + combine + final softmax
    row_fused<<<S, 256>>>(Wout);

    // 5) att_output = att_weight @ v   (W bf16x3  x  V^T bf16x3)
    dim3 gf(D / 64, S / 64, 1);
    gemm_hmma<MODE_F32><<<gf, 128, SMEM_SZ>>>(
        Wh, Wl, VTh, VTl, out, nullptr, nullptr,
        S, D, S, S, S, 0, 0, 0, 0);
}

// round 16
// speedup vs baseline: 1.7576x; 1.4447x over previous
#include <cuda_runtime.h>
#include <cuda_bf16.h>
#include <cuda_fp16.h>
#include <cstdint>

#define S 4096
#define D 512
#define SD (S * D)
#define DD (D * D)
#define PCN 4096  // concatenated projection width (8 * 512)

// ---------------------------------------------------------------------------
// Scratch (__device__ globals; no allocations allowed)
// ---------------------------------------------------------------------------
__device__ __nv_bfloat16 g_Xh[SD], g_Xl[SD];
__device__ __nv_bfloat16 g_WTc_h[8 * DD], g_WTc_l[8 * DD];  // [4096 n][512 k]
__device__ __nv_bfloat16 g_WTv_h[DD], g_WTv_l[DD];          // [512 n][512 k]
__device__ __half g_Pc_h[(size_t)S * PCN], g_Pc_l[(size_t)S * PCN];
__device__ __half g_VTh[SD], g_VTl[SD];                     // [512 n][4096 k]
__device__ float g_S4[4 * (size_t)S * S];
__device__ __half g_Wh[(size_t)S * S];

// ---------------------------------------------------------------------------
// PTX helpers (baseline PTX only; legal on compute_103)
// ---------------------------------------------------------------------------
__device__ __forceinline__ uint32_t smem_u32(const void* p) {
    uint32_t a;
    asm("{ .reg .u64 t; cvta.to.shared.u64 t, %1; cvt.u32.u64 %0, t; }"
        : "=r"(a) : "l"(p));
    return a;
}

#define CP_ASYNC16(dst, src) \
    asm volatile("cp.async.cg.shared.global [%0], [%1], 16;" :: "r"(dst), "l"(src))
#define CP_COMMIT() asm volatile("cp.async.commit_group;" ::: "memory")
#define CP_WAIT1()  asm volatile("cp.async.wait_group 1;" ::: "memory")

__device__ __forceinline__ void ldsm4(uint32_t* r, uint32_t addr) {
    asm volatile("ldmatrix.sync.aligned.m8n8.x4.shared.b16 {%0,%1,%2,%3}, [%4];"
                 : "=r"(r[0]), "=r"(r[1]), "=r"(r[2]), "=r"(r[3]) : "r"(addr));
}

__device__ __forceinline__ void mma_bf16(float* c, const uint32_t* a,
                                         const uint32_t* b) {
    asm volatile(
        "mma.sync.aligned.m16n8k16.row.col.f32.bf16.bf16.f32 "
        "{%0,%1,%2,%3}, {%4,%5,%6,%7}, {%8,%9}, {%0,%1,%2,%3};"
        : "+f"(c[0]), "+f"(c[1]), "+f"(c[2]), "+f"(c[3])
        : "r"(a[0]), "r"(a[1]), "r"(a[2]), "r"(a[3]), "r"(b[0]), "r"(b[1]));
}

__device__ __forceinline__ void mma_f16(float* c, const uint32_t* a,
                                        const uint32_t* b) {
    asm volatile(
        "mma.sync.aligned.m16n8k16.row.col.f32.f16.f16.f32 "
        "{%0,%1,%2,%3}, {%4,%5,%6,%7}, {%8,%9}, {%0,%1,%2,%3};"
        : "+f"(c[0]), "+f"(c[1]), "+f"(c[2]), "+f"(c[3])
        : "r"(a[0]), "r"(a[1]), "r"(a[2]), "r"(a[3]), "r"(b[0]), "r"(b[1]));
}

// swizzled offset within a tile of 64B rows (4 x 16B slots per row)
__device__ __forceinline__ uint32_t swz(int r, int c16) {
    return (uint32_t)(r * 64 + ((c16 ^ ((r >> 1) & 3)) << 4));
}

// ===========================================================================
// KERNEL 1: bf16x3 GEMM (projections).  C = Ah@Bh^T + Ah@Bl^T + Al@Bh^T.
// CTA 64x64, 4 warps (2x2, warp 32x32), K-chunk 32, 3-stage, 4 CTA/SM.
// Emits fp16 hi/lo planes (row-major or transposed).
// ===========================================================================
enum { MODE_SPLIT = 1, MODE_SPLIT_T = 2 };

constexpr int TILE64_B = 4096;    // 64 rows x 64B
constexpr int STAGE3_B = 4 * TILE64_B;  // 16KB: Ah, Al, Bh, Bl
constexpr int OFF_AH = 0;
constexpr int OFF_AL = TILE64_B;
constexpr int OFF_BH = 2 * TILE64_B;
constexpr int OFF_BL = 3 * TILE64_B;
constexpr int SMEM3_SZ = 3 * STAGE3_B;  // 48KB

__device__ __forceinline__ void cp_chunk3(
    uint32_t sbase, int st, const __nv_bfloat16* A0, const __nv_bfloat16* A1,
    const __nv_bfloat16* B0, const __nv_bfloat16* B1, int lda, int ldb,
    int kk, int t) {
    const uint32_t stb = sbase + st * STAGE3_B;
#pragma unroll
    for (int i = 0; i < 2; i++) {
        int e = t + i * 128;
        int r = e >> 2, c16 = e & 3;
        uint32_t o = swz(r, c16);
        CP_ASYNC16(stb + OFF_AH + o,
                   (const char*)(A0 + (size_t)r * lda + kk) + c16 * 16);
        CP_ASYNC16(stb + OFF_AL + o,
                   (const char*)(A1 + (size_t)r * lda + kk) + c16 * 16);
        CP_ASYNC16(stb + OFF_BH + o,
                   (const char*)(B0 + (size_t)r * ldb + kk) + c16 * 16);
        CP_ASYNC16(stb + OFF_BL + o,
                   (const char*)(B1 + (size_t)r * ldb + kk) + c16 * 16);
    }
    CP_COMMIT();
}

template <int MODE>
__global__ void __launch_bounds__(128, 4)
gemm3_bf16(const __nv_bfloat16* __restrict__ Ah, const __nv_bfloat16* __restrict__ Al,
           const __nv_bfloat16* __restrict__ Bh, const __nv_bfloat16* __restrict__ Bl,
           __half* __restrict__ Ch, __half* __restrict__ Cl,
           int Mtot, int Ntot, int K, int lda, int ldb) {
    extern __shared__ char sm[];
    const uint32_t sbase = smem_u32(sm);
    const int t = threadIdx.x, lid = t & 31, wid = t >> 5;
    const int wm = wid & 1, wn = wid >> 1;
    const int m0 = blockIdx.y * 64, n0 = blockIdx.x * 64;

    const __nv_bfloat16* A0 = Ah + (size_t)m0 * lda;
    const __nv_bfloat16* A1 = Al + (size_t)m0 * lda;
    const __nv_bfloat16* B0 = Bh + (size_t)n0 * ldb;
    const __nv_bfloat16* B1 = Bl + (size_t)n0 * ldb;

    float acc[2][4][4];
#pragma unroll
    for (int i = 0; i < 2; i++)
#pragma unroll
        for (int j = 0; j < 4; j++)
#pragma unroll
            for (int k = 0; k < 4; k++) acc[i][j][k] = 0.0f;

    const int NCH = K >> 5;
    const int a_row = lid & 15;
    const int a_chi = lid >> 4;
    const int b_row = (lid & 7) + ((lid >> 4) << 3);
    const int b_chi = (lid >> 3) & 1;

    cp_chunk3(sbase, 0, A0, A1, B0, B1, lda, ldb, 0, t);
    cp_chunk3(sbase, 1, A0, A1, B0, B1, lda, ldb, 32, t);

    for (int c = 0; c < NCH; c++) {
        CP_WAIT1();
        __syncthreads();
        if (c + 2 < NCH)
            cp_chunk3(sbase, (c + 2) % 3, A0, A1, B0, B1, lda, ldb, (c + 2) * 32, t);
        else
            CP_COMMIT();

        const uint32_t base = sbase + (c % 3) * STAGE3_B;
#pragma unroll
        for (int q = 0; q < 2; q++) {
            uint32_t ahf[2][4], alf[2][4], bhf[2][2], blf[2][2];
#pragma unroll
            for (int am = 0; am < 2; am++) {
                int r = wm * 32 + am * 16 + a_row;
                uint32_t off = swz(r, q * 2 + a_chi);
                ldsm4(ahf[am], base + OFF_AH + off);
                ldsm4(alf[am], base + OFF_AL + off);
            }
            {
                int r = wn * 32 + b_row;
                uint32_t off = swz(r, q * 2 + b_chi);
                uint32_t rh[4], rl[4];
                ldsm4(rh, base + OFF_BH + off);
                ldsm4(rl, base + OFF_BL + off);
                bhf[0][0] = rh[0]; bhf[0][1] = rh[1];
                bhf[1][0] = rh[2]; bhf[1][1] = rh[3];
                blf[0][0] = rl[0]; blf[0][1] = rl[1];
                blf[1][0] = rl[2]; blf[1][1] = rl[3];
            }
            uint32_t bhf2[2][2], blf2[2][2];
            {
                int r = wn * 32 + 16 + b_row;
                uint32_t off = swz(r, q * 2 + b_chi);
                uint32_t rh[4], rl[4];
                ldsm4(rh, base + OFF_BH + off);
                ldsm4(rl, base + OFF_BL + off);
                bhf2[0][0] = rh[0]; bhf2[0][1] = rh[1];
                bhf2[1][0] = rh[2]; bhf2[1][1] = rh[3];
                blf2[0][0] = rl[0]; blf2[0][1] = rl[1];
                blf2[1][0] = rl[2]; blf2[1][1] = rl[3];
            }
#pragma unroll
            for (int am = 0; am < 2; am++) {
                mma_bf16(acc[am][0], ahf[am], bhf[0]);
                mma_bf16(acc[am][1], ahf[am], bhf[1]);
                mma_bf16(acc[am][2], ahf[am], bhf2[0]);
                mma_bf16(acc[am][3], ahf[am], bhf2[1]);
            }
#pragma unroll
            for (int am = 0; am < 2; am++) {
                mma_bf16(acc[am][0], ahf[am], blf[0]);
                mma_bf16(acc[am][1], ahf[am], blf[1]);
                mma_bf16(acc[am][2], ahf[am], blf2[0]);
                mma_bf16(acc[am][3], ahf[am], blf2[1]);
            }
#pragma unroll
            for (int am = 0; am < 2; am++) {
                mma_bf16(acc[am][0], alf[am], bhf[0]);
                mma_bf16(acc[am][1], alf[am], bhf[1]);
                mma_bf16(acc[am][2], alf[am], bhf2[0]);
                mma_bf16(acc[am][3], alf[am], bhf2[1]);
            }
        }
    }

    const int t4 = lid >> 2;
    const int n2 = (lid & 3) * 2;
#pragma unroll
    for (int am = 0; am < 2; am++) {
#pragma unroll
        for (int an = 0; an < 4; an++) {
            int m_lo = m0 + wm * 32 + am * 16 + t4;
            int n = n0 + wn * 32 + an * 8 + n2;
            float* a4 = acc[am][an];
            if (MODE == MODE_SPLIT) {
#pragma unroll
                for (int h2 = 0; h2 < 2; h2++) {
                    int m = m_lo + 8 * h2;
                    float v0 = a4[2 * h2], v1 = a4[2 * h2 + 1];
                    __half h0 = __float2half_rn(v0);
                    __half h1 = __float2half_rn(v1);
                    __half2 hh; hh.x = h0; hh.y = h1;
                    __half2 ll;
                    ll.x = __float2half_rn(v0 - __half2float(h0));
                    ll.y = __float2half_rn(v1 - __half2float(h1));
                    *(__half2*)(Ch + (size_t)m * Ntot + n) = hh;
                    *(__half2*)(Cl + (size_t)m * Ntot + n) = ll;
                }
            } else {  // MODE_SPLIT_T
#pragma unroll
                for (int h2 = 0; h2 < 2; h2++) {
                    int m = m_lo + 8 * h2;
#pragma unroll
                    for (int e = 0; e < 2; e++) {
                        float v = a4[2 * h2 + e];
                        __half h = __float2half_rn(v);
                        Ch[(size_t)(n + e) * Mtot + m] = h;
                        Cl[(size_t)(n + e) * Mtot + m] =
                            __float2half_rn(v - __half2float(h));
                    }
                }
            }
        }
    }
}

// ===========================================================================
// KERNEL 2: fp16 2-pass GEMM (scores + final):  C = A@Bh^T + A@Bl^T, fp32 out.
// CTA 64x64, 4 warps, K-chunk 32, 3-stage (12KB/stage, 36KB), 4 CTA/SM.
// tri=1: z==0 keeps n0 <= m0+63; z==1 keeps n0+63 >= m0.
// ===========================================================================
constexpr int STAGE2_B = 3 * TILE64_B;  // 12KB: A, Bh, Bl
constexpr int OFF2_A = 0;
constexpr int OFF2_BH = TILE64_B;
constexpr int OFF2_BL = 2 * TILE64_B;
constexpr int SMEM2_SZ = 3 * STAGE2_B;  // 36KB

__device__ __forceinline__ void cp_chunk2(
    uint32_t sbase, int st, const __half* A0, const __half* B0, const __half* B1,
    int lda, int ldb, int kk, int t) {
    const uint32_t stb = sbase + st * STAGE2_B;
#pragma unroll
    for (int i = 0; i < 2; i++) {
        int e = t + i * 128;
        int r = e >> 2, c16 = e & 3;
        uint32_t o = swz(r, c16);
        CP_ASYNC16(stb + OFF2_A + o,
                   (const char*)(A0 + (size_t)r * lda + kk) + c16 * 16);
        CP_ASYNC16(stb + OFF2_BH + o,
                   (const char*)(B0 + (size_t)r * ldb + kk) + c16 * 16);
        CP_ASYNC16(stb + OFF2_BL + o,
                   (const char*)(B1 + (size_t)r * ldb + kk) + c16 * 16);
    }
    CP_COMMIT();
}

__global__ void __launch_bounds__(128, 4)
gemm2_f16(const __half* __restrict__ A, const __half* __restrict__ Bh,
          const __half* __restrict__ Bl, float* __restrict__ C,
          int Mtot, int Ntot, int K, int lda, int ldb,
          int azoff, int bzoff, long long czoff, int tri) {
    const int m0 = blockIdx.y * 64, n0 = blockIdx.x * 64;
    const size_t z = blockIdx.z;

    if (tri) {
        if (z == 0 && n0 > m0 + 63) return;        // Sl: lower triangle only
        if (z == 1 && n0 + 63 < m0) return;        // Sr: upper triangle only
    }

    extern __shared__ char sm[];
    const uint32_t sbase = smem_u32(sm);
    const int t = threadIdx.x, lid = t & 31, wid = t >> 5;
    const int wm = wid & 1, wn = wid >> 1;

    const __half* A0 = A + (size_t)m0 * lda + z * azoff;
    const __half* B0 = Bh + (size_t)n0 * ldb + z * bzoff;
    const __half* B1 = Bl + (size_t)n0 * ldb + z * bzoff;
    C += z * czoff;

    float acc[2][4][4];
#pragma unroll
    for (int i = 0; i < 2; i++)
#pragma unroll
        for (int j = 0; j < 4; j++)
#pragma unroll
            for (int k = 0; k < 4; k++) acc[i][j][k] = 0.0f;

    const int NCH = K >> 5;
    const int a_row = lid & 15;
    const int a_chi = lid >> 4;
    const int b_row = (lid & 7) + ((lid >> 4) << 3);
    const int b_chi = (lid >> 3) & 1;

    cp_chunk2(sbase, 0, A0, B0, B1, lda, ldb, 0, t);
    cp_chunk2(sbase, 1, A0, B0, B1, lda, ldb, 32, t);

    for (int c = 0; c < NCH; c++) {
        CP_WAIT1();
        __syncthreads();
        if (c + 2 < NCH)
            cp_chunk2(sbase, (c + 2) % 3, A0, B0, B1, lda, ldb, (c + 2) * 32, t);
        else
            CP_COMMIT();

        const uint32_t base = sbase + (c % 3) * STAGE2_B;
#pragma unroll
        for (int q = 0; q < 2; q++) {
            uint32_t af[2][4], bhf[2][2], blf[2][2], bhf2[2][2], blf2[2][2];
#pragma unroll
            for (int am = 0; am < 2; am++) {
                int r = wm * 32 + am * 16 + a_row;
                ldsm4(af[am], base + OFF2_A + swz(r, q * 2 + a_chi));
            }
            {
                int r = wn * 32 + b_row;
                uint32_t off = swz(r, q * 2 + b_chi);
                uint32_t rh[4], rl[4];
                ldsm4(rh, base + OFF2_BH + off);
                ldsm4(rl, base + OFF2_BL + off);
                bhf[0][0] = rh[0]; bhf[0][1] = rh[1];
                bhf[1][0] = rh[2]; bhf[1][1] = rh[3];
                blf[0][0] = rl[0]; blf[0][1] = rl[1];
                blf[1][0] = rl[2]; blf[1][1] = rl[3];
            }
            {
                int r = wn * 32 + 16 + b_row;
                uint32_t off = swz(r, q * 2 + b_chi);
                uint32_t rh[4], rl[4];
                ldsm4(rh, base + OFF2_BH + off);
                ldsm4(rl, base + OFF2_BL + off);
                bhf2[0][0] = rh[0]; bhf2[0][1] = rh[1];
                bhf2[1][0] = rh[2]; bhf2[1][1] = rh[3];
                blf2[0][0] = rl[0]; blf2[0][1] = rl[1];
                blf2[1][0] = rl[2]; blf2[1][1] = rl[3];
            }
#pragma unroll
            for (int am = 0; am < 2; am++) {
                mma_f16(acc[am][0], af[am], bhf[0]);
                mma_f16(acc[am][1], af[am], bhf[1]);
                mma_f16(acc[am][2], af[am], bhf2[0]);
                mma_f16(acc[am][3], af[am], bhf2[1]);
            }
#pragma unroll
            for (int am = 0; am < 2; am++) {
                mma_f16(acc[am][0], af[am], blf[0]);
                mma_f16(acc[am][1], af[am], blf[1]);
                mma_f16(acc[am][2], af[am], blf2[0]);
                mma_f16(acc[am][3], af[am], blf2[1]);
            }
        }
    }

    const int t4 = lid >> 2;
    const int n2 = (lid & 3) * 2;
#pragma unroll
    for (int am = 0; am < 2; am++) {
#pragma unroll
        for (int an = 0; an < 4; an++) {
            int m_lo = m0 + wm * 32 + am * 16 + t4;
            int n = n0 + wn * 32 + an * 8 + n2;
            float* a4 = acc[am][an];
            __stcs((float2*)(C + (size_t)m_lo * Ntot + n),
                   make_float2(a4[0], a4[1]));
            __stcs((float2*)(C + (size_t)(m_lo + 8) * Ntot + n),
                   make_float2(a4[2], a4[3]));
        }
    }
}

// ---------------------------------------------------------------------------
// splits
// ---------------------------------------------------------------------------
__global__ void split_x(const float* __restrict__ x, __nv_bfloat16* __restrict__ xh,
                        __nv_bfloat16* __restrict__ xl) {
    int i = blockIdx.x * 256 + threadIdx.x;
    float v = x[i];
    __nv_bfloat16 h = __float2bfloat16(v);
    xh[i] = h;
    xl[i] = __float2bfloat16(v - __bfloat162float(h));
}

struct W9 { const float* p[9]; };

__global__ void splitT_all(W9 w9, __nv_bfloat16* __restrict__ WTc_h,
                           __nv_bfloat16* __restrict__ WTc_l,
                           __nv_bfloat16* __restrict__ WTv_h,
                           __nv_bfloat16* __restrict__ WTv_l) {
    __shared__ float tile[32][33];
    const int tx = threadIdx.x, ty = threadIdx.y;
    const int kt = blockIdx.x * 32, nt = blockIdx.y * 32;
    const int wi = blockIdx.z;
    const float* w = w9.p[wi];
#pragma unroll
    for (int j = 0; j < 4; j++) {
        int r = ty + 8 * j;
        tile[r][tx] = w[(size_t)(kt + r) * D + nt + tx];
    }
    __syncthreads();
#pragma unroll
    for (int j = 0; j < 4; j++) {
        int n_loc = ty + 8 * j;
        float v = tile[tx][n_loc];
        __nv_bfloat16 h = __float2bfloat16(v);
        __nv_bfloat16 l = __float2bfloat16(v - __bfloat162float(h));
        if (wi < 8) {
            size_t o = (size_t)(wi * 512 + nt + n_loc) * D + kt + tx;
            WTc_h[o] = h;
            WTc_l[o] = l;
        } else {
            size_t o = (size_t)(nt + n_loc) * D + kt + tx;
            WTv_h[o] = h;
            WTv_l[o] = l;
        }
    }
}

// ---------------------------------------------------------------------------
// warp-shuffle block helpers (256 threads, 8 warps)
// ---------------------------------------------------------------------------
__device__ __forceinline__ float wmax(float v) {
#pragma unroll
    for (int o = 16; o; o >>= 1) v = fmaxf(v, __shfl_xor_sync(0xffffffffu, v, o));
    return v;
}
__device__ __forceinline__ float blockMax8(float v, float* sw, int w, int l) {
    v = wmax(v);
    if (l == 0) sw[w] = v;
    __syncthreads();
    float r = sw[0];
#pragma unroll
    for (int k = 1; k < 8; k++) r = fmaxf(r, sw[k]);
    __syncthreads();
    return r;
}
__device__ __forceinline__ float blockSum8(float v, float* sw, int w, int l) {
#pragma unroll
    for (int o = 16; o; o >>= 1) v += __shfl_xor_sync(0xffffffffu, v, o);
    if (l == 0) sw[w] = v;
    __syncthreads();
    float r = 0.0f;
#pragma unroll
    for (int k = 0; k < 8; k++) r += sw[k];
    __syncthreads();
    return r;
}
__device__ __forceinline__ float blockScanExcl(float s, float* sw, int w, int l,
                                               float* tot) {
    float incl = s;
#pragma unroll
    for (int o = 1; o < 32; o <<= 1) {
        float x = __shfl_up_sync(0xffffffffu, incl, o);
        if (l >= o) incl += x;
    }
    if (l == 31) sw[w] = incl;
    __syncthreads();
    float woff = 0.0f, tt = 0.0f;
#pragma unroll
    for (int k = 0; k < 8; k++) {
        float sv = sw[k];
        tt += sv;
        if (k < w) woff += sv;
    }
    __syncthreads();
    *tot = tt;
    return incl - s + woff;
}

// ---------------------------------------------------------------------------
// Fused per-row pipeline (emits fp32 att_weight + fp16 Wh plane)
// ---------------------------------------------------------------------------
__global__ __launch_bounds__(256) void row_fused(float* __restrict__ Wout) {
    __shared__ float sw[8];
    const int i = blockIdx.x;
    const int t = threadIdx.x;
    const int w = t >> 5, l = t & 31;
    const int j0 = t * 16;
    const float inv_norm = 0.04419417382415922f;  // 1/sqrt(512)

    const float* Sl = g_S4 + 0 * (size_t)S * S + (size_t)i * S;
    const float* Sr = g_S4 + 1 * (size_t)S * S + (size_t)i * S;
    const float* Sg = g_S4 + 2 * (size_t)S * S + (size_t)i * S;
    const float* Sp = g_S4 + 3 * (size_t)S * S + (size_t)i * S;

    float lcdf[16], rcdf[16];

    {  // left boundary (uses only j <= i)
        float e[16];
        float m = -1e30f;
        float lsum = 0.0f;
        if (j0 <= i) {
#pragma unroll
            for (int u4 = 0; u4 < 4; u4++) {
                float4 v = __ldcs(reinterpret_cast<const float4*>(Sl + j0 + 4 * u4));
                e[4 * u4 + 0] = v.x; e[4 * u4 + 1] = v.y;
                e[4 * u4 + 2] = v.z; e[4 * u4 + 3] = v.w;
            }
#pragma unroll
            for (int u = 0; u < 16; u++) {
                int j = j0 + u;
                float s = (j <= i) ? e[u] * inv_norm : -1e30f;
                e[u] = s;
                m = fmaxf(m, s);
            }
        } else {
#pragma unroll
            for (int u = 0; u < 16; u++) e[u] = -1e30f;
        }
        m = blockMax8(m, sw, w, l);
        if (j0 <= i) {
#pragma unroll
            for (int u = 0; u < 16; u++) {
                int j = j0 + u;
                float ev = (j <= i) ? __expf(e[u] - m) : 0.0f;
                e[u] = ev;
                lsum += ev;
            }
        } else {
#pragma unroll
            for (int u = 0; u < 16; u++) e[u] = 0.0f;
        }
        float tot;
        float off = blockScanExcl(lsum, sw, w, l, &tot);
        float inv = 1.0f / tot;
        float c = 0.0f;
#pragma unroll
        for (int u = 0; u < 16; u++) {
            c += e[u];
            lcdf[u] = (c + off) * inv;
        }
    }

    {  // right boundary (uses only j >= i)
        float e[16];
        float m = -1e30f;
        float rsum = 0.0f;
        if (j0 + 15 >= i) {
#pragma unroll
            for (int u4 = 0; u4 < 4; u4++) {
                float4 v = __ldcs(reinterpret_cast<const float4*>(Sr + j0 + 4 * u4));
                e[4 * u4 + 0] = v.x; e[4 * u4 + 1] = v.y;
                e[4 * u4 + 2] = v.z; e[4 * u4 + 3] = v.w;
            }
#pragma unroll
            for (int u = 0; u < 16; u++) {
                int j = j0 + u;
                float s = (j >= i) ? e[u] * inv_norm : -1e30f;
                e[u] = s;
                m = fmaxf(m, s);
            }
        } else {
#pragma unroll
            for (int u = 0; u < 16; u++) e[u] = -1e30f;
        }
        m = blockMax8(m, sw, w, l);
        if (j0 + 15 >= i) {
#pragma unroll
            for (int u = 0; u < 16; u++) {
                int j = j0 + u;
                float ev = (j >= i) ? __expf(e[u] - m) : 0.0f;
                e[u] = ev;
                rsum += ev;
            }
        } else {
#pragma unroll
            for (int u = 0; u < 16; u++) e[u] = 0.0f;
        }
        float tot;
        float excl = blockScanExcl(rsum, sw, w, l, &tot);
        float suff = tot - excl - rsum;
        float inv = 1.0f / tot;
        float c = 0.0f;
#pragma unroll
        for (int u = 15; u >= 0; u--) {
            c += e[u];
            rcdf[u] = (c + suff) * inv;
        }
    }

    {  // combine + final softmax
        float wv[16], p[16];
#pragma unroll
        for (int u4 = 0; u4 < 4; u4++) {
            float4 vg = __ldcs(reinterpret_cast<const float4*>(Sg + j0 + 4 * u4));
            float4 vp = __ldcs(reinterpret_cast<const float4*>(Sp + j0 + 4 * u4));
            wv[4 * u4 + 0] = vg.x; wv[4 * u4 + 1] = vg.y;
            wv[4 * u4 + 2] = vg.z; wv[4 * u4 + 3] = vg.w;
            p[4 * u4 + 0] = vp.x; p[4 * u4 + 1] = vp.y;
            p[4 * u4 + 2] = vp.z; p[4 * u4 + 3] = vp.w;
        }
        float m = -1e30f;
#pragma unroll
        for (int u = 0; u < 16; u++) {
            float sc = (wv[u] + p[u] * lcdf[u] * rcdf[u]) * inv_norm;
            wv[u] = sc;
            m = fmaxf(m, sc);
        }
        m = blockMax8(m, sw, w, l);
        float lsum = 0.0f;
#pragma unroll
        for (int u = 0; u < 16; u++) {
            float ev = __expf(wv[u] - m);
            wv[u] = ev;
            lsum += ev;
        }
        float tot = blockSum8(lsum, sw, w, l);
        float inv = 1.0f / tot;
        float* Wrow = Wout + (size_t)i * S + j0;
        __half* Hrow = g_Wh + (size_t)i * S + j0;
#pragma unroll
        for (int u4 = 0; u4 < 4; u4++) {
            float4 o;
            o.x = wv[4 * u4 + 0] * inv;
            o.y = wv[4 * u4 + 1] * inv;
            o.z = wv[4 * u4 + 2] * inv;
            o.w = wv[4 * u4 + 3] * inv;
            *reinterpret_cast<float4*>(Wrow + 4 * u4) = o;
            __half2 h01, h23;
            h01.x = __float2half_rn(o.x); h01.y = __float2half_rn(o.y);
            h23.x = __float2half_rn(o.z); h23.y = __float2half_rn(o.w);
            *(__half2*)(Hrow + 4 * u4 + 0) = h01;
            *(__half2*)(Hrow + 4 * u4 + 2) = h23;
        }
    }
}

// ---------------------------------------------------------------------------
// Launch. inputs: x, w_ql, w_kl, w_qr, w_kr, w_qg, w_kg, w_qloc, w_kloc, w_v
// Output layout: [att_output (S*D) | att_weight (S*S)]
// ---------------------------------------------------------------------------
extern "C" void kernel_launch(void* const* d_in, const int* in_sizes, int n_in,
                              void* d_out, int out_size) {
    const float* x = (const float*)d_in[0];
    W9 w9;
    for (int i = 0; i < 9; i++) w9.p[i] = (const float*)d_in[1 + i];

    float* out = (float*)d_out;
    float* Wout = out + SD;

    __nv_bfloat16 *Xh, *Xl, *WTc_h, *WTc_l, *WTv_h, *WTv_l;
    __half *Pc_h, *Pc_l, *VTh, *VTl, *Wh;
    float* S4;
    cudaGetSymbolAddress((void**)&Xh, g_Xh);
    cudaGetSymbolAddress((void**)&Xl, g_Xl);
    cudaGetSymbolAddress((void**)&WTc_h, g_WTc_h);
    cudaGetSymbolAddress((void**)&WTc_l, g_WTc_l);
    cudaGetSymbolAddress((void**)&WTv_h, g_WTv_h);
    cudaGetSymbolAddress((void**)&WTv_l, g_WTv_l);
    cudaGetSymbolAddress((void**)&Pc_h, g_Pc_h);
    cudaGetSymbolAddress((void**)&Pc_l, g_Pc_l);
    cudaGetSymbolAddress((void**)&VTh, g_VTh);
    cudaGetSymbolAddress((void**)&VTl, g_VTl);
    cudaGetSymbolAddress((void**)&S4, g_S4);
    cudaGetSymbolAddress((void**)&Wh, g_Wh);

    cudaFuncSetAttribute(gemm3_bf16<MODE_SPLIT>,
                         cudaFuncAttributeMaxDynamicSharedMemorySize, SMEM3_SZ);
    cudaFuncSetAttribute(gemm3_bf16<MODE_SPLIT_T>,
                         cudaFuncAttributeMaxDynamicSharedMemorySize, SMEM3_SZ);
    cudaFuncSetAttribute(gemm2_f16,
                         cudaFuncAttributeMaxDynamicSharedMemorySize, SMEM2_SZ);

    // 1) splits
    split_x<<<SD / 256, 256>>>(x, Xh, Xl);
    dim3 tb(32, 8);
    dim3 tg(D / 32, D / 32, 9);
    splitT_all<<<tg, tb>>>(w9, WTc_h, WTc_l, WTv_h, WTv_l);

    // 2) projections (bf16x3 -> fp16 hi/lo planes)
    dim3 gp(PCN / 64, S / 64, 1);
    gemm3_bf16<MODE_SPLIT><<<gp, 128, SMEM3_SZ>>>(
        Xh, Xl, WTc_h, WTc_l, Pc_h, Pc_l, S, PCN, D, D, D);

    dim3 gv(D / 64, S / 64, 1);
    gemm3_bf16<MODE_SPLIT_T><<<gv, 128, SMEM3_SZ>>>(
        Xh, Xl, WTv_h, WTv_l, VTh, VTl, S, D, D, D, D);

    // 3) four S x S score matrices, fp16 2-pass, one batched launch;
    //    z=0 (Sl) lower-triangle blocks only, z=1 (Sr) upper-triangle only.
    dim3 gs(S / 64, S / 64, 4);
    gemm2_f16<<<gs, 128, SMEM2_SZ>>>(
        Pc_h, Pc_h + 512, Pc_l + 512, S4,
        S, S, D, PCN, PCN, 1024, 1024, (long long)S * S, 1);

    // 4) fused boundary softmaxes + cumsums + combine + final softmax
    row_fused<<<S, 256>>>(Wout);

    // 5) att_output = att_weight @ v  (fp16 2-pass)
    dim3 gf(D / 64, S / 64, 1);
    gemm2_f16<<<gf, 128, SMEM2_SZ>>>(
        Wh, VTh, VTl, out, S, D, S, S, S, 0, 0, 0, 0);
}

// round 17
// speedup vs baseline: 2.3617x; 1.3437x over previous
#include <cuda_runtime.h>
#include <cuda_bf16.h>
#include <cuda_fp16.h>
#include <cstdint>

#define S 4096
#define D 512
#define SD (S * D)
#define DD (D * D)
#define PCN 4096  // concatenated projection width (8 * 512)

// ---------------------------------------------------------------------------
// Scratch (__device__ globals; no allocations allowed)
// ---------------------------------------------------------------------------
__device__ __nv_bfloat16 g_Xh[SD], g_Xl[SD];
__device__ __nv_bfloat16 g_WTc_h[8 * DD], g_WTc_l[8 * DD];  // [4096 n][512 k]
__device__ __nv_bfloat16 g_WTv_h[DD], g_WTv_l[DD];          // [512 n][512 k]
__device__ __half g_Pc[(size_t)S * PCN];                    // fp16 q/k planes
__device__ __half g_VT[SD];                                 // [512 n][4096 k]
__device__ float g_S4[4 * (size_t)S * S];
__device__ __half g_Wh[(size_t)S * S];

// ---------------------------------------------------------------------------
// PTX helpers (baseline PTX only; legal on compute_103)
// ---------------------------------------------------------------------------
__device__ __forceinline__ uint32_t smem_u32(const void* p) {
    uint32_t a;
    asm("{ .reg .u64 t; cvta.to.shared.u64 t, %1; cvt.u32.u64 %0, t; }"
        : "=r"(a) : "l"(p));
    return a;
}

#define CP_ASYNC16(dst, src) \
    asm volatile("cp.async.cg.shared.global [%0], [%1], 16;" :: "r"(dst), "l"(src))
#define CP_COMMIT() asm volatile("cp.async.commit_group;" ::: "memory")
#define CP_WAIT1()  asm volatile("cp.async.wait_group 1;" ::: "memory")

__device__ __forceinline__ void ldsm4(uint32_t* r, uint32_t addr) {
    asm volatile("ldmatrix.sync.aligned.m8n8.x4.shared.b16 {%0,%1,%2,%3}, [%4];"
                 : "=r"(r[0]), "=r"(r[1]), "=r"(r[2]), "=r"(r[3]) : "r"(addr));
}

__device__ __forceinline__ void mma_bf16(float* c, const uint32_t* a,
                                         const uint32_t* b) {
    asm volatile(
        "mma.sync.aligned.m16n8k16.row.col.f32.bf16.bf16.f32 "
        "{%0,%1,%2,%3}, {%4,%5,%6,%7}, {%8,%9}, {%0,%1,%2,%3};"
        : "+f"(c[0]), "+f"(c[1]), "+f"(c[2]), "+f"(c[3])
        : "r"(a[0]), "r"(a[1]), "r"(a[2]), "r"(a[3]), "r"(b[0]), "r"(b[1]));
}

__device__ __forceinline__ void mma_f16(float* c, const uint32_t* a,
                                        const uint32_t* b) {
    asm volatile(
        "mma.sync.aligned.m16n8k16.row.col.f32.f16.f16.f32 "
        "{%0,%1,%2,%3}, {%4,%5,%6,%7}, {%8,%9}, {%0,%1,%2,%3};"
        : "+f"(c[0]), "+f"(c[1]), "+f"(c[2]), "+f"(c[3])
        : "r"(a[0]), "r"(a[1]), "r"(a[2]), "r"(a[3]), "r"(b[0]), "r"(b[1]));
}

// swizzle for 64B rows (4 x 16B slots)
__device__ __forceinline__ uint32_t swz(int r, int c16) {
    return (uint32_t)(r * 64 + ((c16 ^ ((r >> 1) & 3)) << 4));
}
// swizzle for 128B rows (8 x 16B slots)
__device__ __forceinline__ uint32_t swz128(int r, int c16) {
    return (uint32_t)(r * 128 + ((c16 ^ (r & 7)) << 4));
}

// ===========================================================================
// KERNEL 1: bf16x3 GEMM (projections).  C = Ah@Bh^T + Ah@Bl^T + Al@Bh^T.
// CTA 64x64, 4 warps (2x2, warp 32x32), K-chunk 32, 3-stage, 4 CTA/SM.
// Emits ONE fp16 plane (row-major or transposed).
// ===========================================================================
enum { MODE_SPLIT = 1, MODE_SPLIT_T = 2 };

constexpr int TILE64_B = 4096;          // 64 rows x 64B
constexpr int STAGE3_B = 4 * TILE64_B;  // 16KB: Ah, Al, Bh, Bl
constexpr int OFF_AH = 0;
constexpr int OFF_AL = TILE64_B;
constexpr int OFF_BH = 2 * TILE64_B;
constexpr int OFF_BL = 3 * TILE64_B;
constexpr int SMEM3_SZ = 3 * STAGE3_B;  // 48KB

__device__ __forceinline__ void cp_chunk3(
    uint32_t sbase, int st, const __nv_bfloat16* A0, const __nv_bfloat16* A1,
    const __nv_bfloat16* B0, const __nv_bfloat16* B1, int lda, int ldb,
    int kk, int t) {
    const uint32_t stb = sbase + st * STAGE3_B;
#pragma unroll
    for (int i = 0; i < 2; i++) {
        int e = t + i * 128;
        int r = e >> 2, c16 = e & 3;
        uint32_t o = swz(r, c16);
        CP_ASYNC16(stb + OFF_AH + o,
                   (const char*)(A0 + (size_t)r * lda + kk) + c16 * 16);
        CP_ASYNC16(stb + OFF_AL + o,
                   (const char*)(A1 + (size_t)r * lda + kk) + c16 * 16);
        CP_ASYNC16(stb + OFF_BH + o,
                   (const char*)(B0 + (size_t)r * ldb + kk) + c16 * 16);
        CP_ASYNC16(stb + OFF_BL + o,
                   (const char*)(B1 + (size_t)r * ldb + kk) + c16 * 16);
    }
    CP_COMMIT();
}

template <int MODE>
__global__ void __launch_bounds__(128, 4)
gemm3_bf16(const __nv_bfloat16* __restrict__ Ah, const __nv_bfloat16* __restrict__ Al,
           const __nv_bfloat16* __restrict__ Bh, const __nv_bfloat16* __restrict__ Bl,
           __half* __restrict__ Ch, int Mtot, int Ntot, int K, int lda, int ldb) {
    extern __shared__ char sm[];
    const uint32_t sbase = smem_u32(sm);
    const int t = threadIdx.x, lid = t & 31, wid = t >> 5;
    const int wm = wid & 1, wn = wid >> 1;
    const int m0 = blockIdx.y * 64, n0 = blockIdx.x * 64;

    const __nv_bfloat16* A0 = Ah + (size_t)m0 * lda;
    const __nv_bfloat16* A1 = Al + (size_t)m0 * lda;
    const __nv_bfloat16* B0 = Bh + (size_t)n0 * ldb;
    const __nv_bfloat16* B1 = Bl + (size_t)n0 * ldb;

    float acc[2][4][4];
#pragma unroll
    for (int i = 0; i < 2; i++)
#pragma unroll
        for (int j = 0; j < 4; j++)
#pragma unroll
            for (int k = 0; k < 4; k++) acc[i][j][k] = 0.0f;

    const int NCH = K >> 5;
    const int a_row = lid & 15;
    const int a_chi = lid >> 4;
    const int b_row = (lid & 7) + ((lid >> 4) << 3);
    const int b_chi = (lid >> 3) & 1;

    cp_chunk3(sbase, 0, A0, A1, B0, B1, lda, ldb, 0, t);
    cp_chunk3(sbase, 1, A0, A1, B0, B1, lda, ldb, 32, t);

    for (int c = 0; c < NCH; c++) {
        CP_WAIT1();
        __syncthreads();
        if (c + 2 < NCH)
            cp_chunk3(sbase, (c + 2) % 3, A0, A1, B0, B1, lda, ldb, (c + 2) * 32, t);
        else
            CP_COMMIT();

        const uint32_t base = sbase + (c % 3) * STAGE3_B;
#pragma unroll
        for (int q = 0; q < 2; q++) {
            uint32_t ahf[2][4], alf[2][4], bhf[2][2], blf[2][2];
#pragma unroll
            for (int am = 0; am < 2; am++) {
                int r = wm * 32 + am * 16 + a_row;
                uint32_t off = swz(r, q * 2 + a_chi);
                ldsm4(ahf[am], base + OFF_AH + off);
                ldsm4(alf[am], base + OFF_AL + off);
            }
            {
                int r = wn * 32 + b_row;
                uint32_t off = swz(r, q * 2 + b_chi);
                uint32_t rh[4], rl[4];
                ldsm4(rh, base + OFF_BH + off);
                ldsm4(rl, base + OFF_BL + off);
                bhf[0][0] = rh[0]; bhf[0][1] = rh[1];
                bhf[1][0] = rh[2]; bhf[1][1] = rh[3];
                blf[0][0] = rl[0]; blf[0][1] = rl[1];
                blf[1][0] = rl[2]; blf[1][1] = rl[3];
            }
            uint32_t bhf2[2][2], blf2[2][2];
            {
                int r = wn * 32 + 16 + b_row;
                uint32_t off = swz(r, q * 2 + b_chi);
                uint32_t rh[4], rl[4];
                ldsm4(rh, base + OFF_BH + off);
                ldsm4(rl, base + OFF_BL + off);
                bhf2[0][0] = rh[0]; bhf2[0][1] = rh[1];
                bhf2[1][0] = rh[2]; bhf2[1][1] = rh[3];
                blf2[0][0] = rl[0]; blf2[0][1] = rl[1];
                blf2[1][0] = rl[2]; blf2[1][1] = rl[3];
            }
#pragma unroll
            for (int am = 0; am < 2; am++) {
                mma_bf16(acc[am][0], ahf[am], bhf[0]);
                mma_bf16(acc[am][1], ahf[am], bhf[1]);
                mma_bf16(acc[am][2], ahf[am], bhf2[0]);
                mma_bf16(acc[am][3], ahf[am], bhf2[1]);
            }
#pragma unroll
            for (int am = 0; am < 2; am++) {
                mma_bf16(acc[am][0], ahf[am], blf[0]);
                mma_bf16(acc[am][1], ahf[am], blf[1]);
                mma_bf16(acc[am][2], ahf[am], blf2[0]);
                mma_bf16(acc[am][3], ahf[am], blf2[1]);
            }
#pragma unroll
            for (int am = 0; am < 2; am++) {
                mma_bf16(acc[am][0], alf[am], bhf[0]);
                mma_bf16(acc[am][1], alf[am], bhf[1]);
                mma_bf16(acc[am][2], alf[am], bhf2[0]);
                mma_bf16(acc[am][3], alf[am], bhf2[1]);
            }
        }
    }

    const int t4 = lid >> 2;
    const int n2 = (lid & 3) * 2;
#pragma unroll
    for (int am = 0; am < 2; am++) {
#pragma unroll
        for (int an = 0; an < 4; an++) {
            int m_lo = m0 + wm * 32 + am * 16 + t4;
            int n = n0 + wn * 32 + an * 8 + n2;
            float* a4 = acc[am][an];
            if (MODE == MODE_SPLIT) {
#pragma unroll
                for (int h2 = 0; h2 < 2; h2++) {
                    int m = m_lo + 8 * h2;
                    __half2 hh;
                    hh.x = __float2half_rn(a4[2 * h2 + 0]);
                    hh.y = __float2half_rn(a4[2 * h2 + 1]);
                    *(__half2*)(Ch + (size_t)m * Ntot + n) = hh;
                }
            } else {  // MODE_SPLIT_T
#pragma unroll
                for (int h2 = 0; h2 < 2; h2++) {
                    int m = m_lo + 8 * h2;
#pragma unroll
                    for (int e = 0; e < 2; e++)
                        Ch[(size_t)(n + e) * Mtot + m] =
                            __float2half_rn(a4[2 * h2 + e]);
                }
            }
        }
    }
}

// ===========================================================================
// KERNEL 2: single-pass fp16 GEMM (scores + final):  C = A@B^T, fp32 out.
// CTA 64x64, 4 warps, K-chunk 64 (128B rows), 3-stage (16KB/stage, 48KB),
// 4 CTA/SM.  tri=1: z==0 keeps n0 <= m0+63; z==1 keeps n0+63 >= m0.
// ===========================================================================
constexpr int TILE128_B = 8192;            // 64 rows x 128B
constexpr int STAGE1_B = 2 * TILE128_B;    // 16KB: A, B
constexpr int OFF1_A = 0;
constexpr int OFF1_B = TILE128_B;
constexpr int SMEM1_SZ = 3 * STAGE1_B;     // 48KB

__device__ __forceinline__ void cp_chunk1(
    uint32_t sbase, int st, const __half* A0, const __half* B0,
    int lda, int ldb, int kk, int t) {
    const uint32_t stb = sbase + st * STAGE1_B;
#pragma unroll
    for (int i = 0; i < 4; i++) {
        int e = t + i * 128;
        int r = e >> 3, c16 = e & 7;
        uint32_t o = swz128(r, c16);
        CP_ASYNC16(stb + OFF1_A + o,
                   (const char*)(A0 + (size_t)r * lda + kk) + c16 * 16);
        CP_ASYNC16(stb + OFF1_B + o,
                   (const char*)(B0 + (size_t)r * ldb + kk) + c16 * 16);
    }
    CP_COMMIT();
}

__global__ void __launch_bounds__(128, 4)
gemm1_f16(const __half* __restrict__ A, const __half* __restrict__ B,
          float* __restrict__ C, int Mtot, int Ntot, int K, int lda, int ldb,
          int azoff, int bzoff, long long czoff, int tri) {
    const int m0 = blockIdx.y * 64, n0 = blockIdx.x * 64;
    const size_t z = blockIdx.z;

    if (tri) {
        if (z == 0 && n0 > m0 + 63) return;        // Sl: lower triangle only
        if (z == 1 && n0 + 63 < m0) return;        // Sr: upper triangle only
    }

    extern __shared__ char sm[];
    const uint32_t sbase = smem_u32(sm);
    const int t = threadIdx.x, lid = t & 31, wid = t >> 5;
    const int wm = wid & 1, wn = wid >> 1;

    const __half* A0 = A + (size_t)m0 * lda + z * azoff;
    const __half* B0 = B + (size_t)n0 * ldb + z * bzoff;
    C += z * czoff;

    float acc[2][4][4];
#pragma unroll
    for (int i = 0; i < 2; i++)
#pragma unroll
        for (int j = 0; j < 4; j++)
#pragma unroll
            for (int k = 0; k < 4; k++) acc[i][j][k] = 0.0f;

    const int NCH = K >> 6;  // 64-wide chunks
    const int a_row = lid & 15;
    const int a_chi = lid >> 4;
    const int b_row = (lid & 7) + ((lid >> 4) << 3);
    const int b_chi = (lid >> 3) & 1;

    cp_chunk1(sbase, 0, A0, B0, lda, ldb, 0, t);
    cp_chunk1(sbase, 1, A0, B0, lda, ldb, 64, t);

    for (int c = 0; c < NCH; c++) {
        CP_WAIT1();
        __syncthreads();
        if (c + 2 < NCH)
            cp_chunk1(sbase, (c + 2) % 3, A0, B0, lda, ldb, (c + 2) * 64, t);
        else
            CP_COMMIT();

        const uint32_t base = sbase + (c % 3) * STAGE1_B;
#pragma unroll
        for (int q = 0; q < 4; q++) {
            uint32_t af[2][4], bf[2][2], bf2[2][2];
#pragma unroll
            for (int am = 0; am < 2; am++) {
                int r = wm * 32 + am * 16 + a_row;
                ldsm4(af[am], base + OFF1_A + swz128(r, q * 2 + a_chi));
            }
            {
                int r = wn * 32 + b_row;
                uint32_t rb[4];
                ldsm4(rb, base + OFF1_B + swz128(r, q * 2 + b_chi));
                bf[0][0] = rb[0]; bf[0][1] = rb[1];
                bf[1][0] = rb[2]; bf[1][1] = rb[3];
            }
            {
                int r = wn * 32 + 16 + b_row;
                uint32_t rb[4];
                ldsm4(rb, base + OFF1_B + swz128(r, q * 2 + b_chi));
                bf2[0][0] = rb[0]; bf2[0][1] = rb[1];
                bf2[1][0] = rb[2]; bf2[1][1] = rb[3];
            }
#pragma unroll
            for (int am = 0; am < 2; am++) {
                mma_f16(acc[am][0], af[am], bf[0]);
                mma_f16(acc[am][1], af[am], bf[1]);
                mma_f16(acc[am][2], af[am], bf2[0]);
                mma_f16(acc[am][3], af[am], bf2[1]);
            }
        }
    }

    const int t4 = lid >> 2;
    const int n2 = (lid & 3) * 2;
#pragma unroll
    for (int am = 0; am < 2; am++) {
#pragma unroll
        for (int an = 0; an < 4; an++) {
            int m_lo = m0 + wm * 32 + am * 16 + t4;
            int n = n0 + wn * 32 + an * 8 + n2;
            float* a4 = acc[am][an];
            __stcs((float2*)(C + (size_t)m_lo * Ntot + n),
                   make_float2(a4[0], a4[1]));
            __stcs((float2*)(C + (size_t)(m_lo + 8) * Ntot + n),
                   make_float2(a4[2], a4[3]));
        }
    }
}

// ---------------------------------------------------------------------------
// splits
// ---------------------------------------------------------------------------
__global__ void split_x(const float* __restrict__ x, __nv_bfloat16* __restrict__ xh,
                        __nv_bfloat16* __restrict__ xl) {
    int i = blockIdx.x * 256 + threadIdx.x;
    float v = x[i];
    __nv_bfloat16 h = __float2bfloat16(v);
    xh[i] = h;
    xl[i] = __float2bfloat16(v - __bfloat162float(h));
}

struct W9 { const float* p[9]; };

__global__ void splitT_all(W9 w9, __nv_bfloat16* __restrict__ WTc_h,
                           __nv_bfloat16* __restrict__ WTc_l,
                           __nv_bfloat16* __restrict__ WTv_h,
                           __nv_bfloat16* __restrict__ WTv_l) {
    __shared__ float tile[32][33];
    const int tx = threadIdx.x, ty = threadIdx.y;
    const int kt = blockIdx.x * 32, nt = blockIdx.y * 32;
    const int wi = blockIdx.z;
    const float* w = w9.p[wi];
#pragma unroll
    for (int j = 0; j < 4; j++) {
        int r = ty + 8 * j;
        tile[r][tx] = w[(size_t)(kt + r) * D + nt + tx];
    }
    __syncthreads();
#pragma unroll
    for (int j = 0; j < 4; j++) {
        int n_loc = ty + 8 * j;
        float v = tile[tx][n_loc];
        __nv_bfloat16 h = __float2bfloat16(v);
        __nv_bfloat16 l = __float2bfloat16(v - __bfloat162float(h));
        if (wi < 8) {
            size_t o = (size_t)(wi * 512 + nt + n_loc) * D + kt + tx;
            WTc_h[o] = h;
            WTc_l[o] = l;
        } else {
            size_t o = (size_t)(nt + n_loc) * D + kt + tx;
            WTv_h[o] = h;
            WTv_l[o] = l;
        }
    }
}

// ---------------------------------------------------------------------------
// warp-shuffle block helpers (256 threads, 8 warps)
// ---------------------------------------------------------------------------
__device__ __forceinline__ float wmax(float v) {
#pragma unroll
    for (int o = 16; o; o >>= 1) v = fmaxf(v, __shfl_xor_sync(0xffffffffu, v, o));
    return v;
}
__device__ __forceinline__ float blockMax8(float v, float* sw, int w, int l) {
    v = wmax(v);
    if (l == 0) sw[w] = v;
    __syncthreads();
    float r = sw[0];
#pragma unroll
    for (int k = 1; k < 8; k++) r = fmaxf(r, sw[k]);
    __syncthreads();
    return r;
}
__device__ __forceinline__ float blockSum8(float v, float* sw, int w, int l) {
#pragma unroll
    for (int o = 16; o; o >>= 1) v += __shfl_xor_sync(0xffffffffu, v, o);
    if (l == 0) sw[w] = v;
    __syncthreads();
    float r = 0.0f;
#pragma unroll
    for (int k = 0; k < 8; k++) r += sw[k];
    __syncthreads();
    return r;
}
__device__ __forceinline__ float blockScanExcl(float s, float* sw, int w, int l,
                                               float* tot) {
    float incl = s;
#pragma unroll
    for (int o = 1; o < 32; o <<= 1) {
        float x = __shfl_up_sync(0xffffffffu, incl, o);
        if (l >= o) incl += x;
    }
    if (l == 31) sw[w] = incl;
    __syncthreads();
    float woff = 0.0f, tt = 0.0f;
#pragma unroll
    for (int k = 0; k < 8; k++) {
        float sv = sw[k];
        tt += sv;
        if (k < w) woff += sv;
    }
    __syncthreads();
    *tot = tt;
    return incl - s + woff;
}

// ---------------------------------------------------------------------------
// Fused per-row pipeline (emits fp32 att_weight + fp16 Wh plane)
// ---------------------------------------------------------------------------
__global__ __launch_bounds__(256) void row_fused(float* __restrict__ Wout) {
    __shared__ float sw[8];
    const int i = blockIdx.x;
    const int t = threadIdx.x;
    const int w = t >> 5, l = t & 31;
    const int j0 = t * 16;
    const float inv_norm = 0.04419417382415922f;  // 1/sqrt(512)

    const float* Sl = g_S4 + 0 * (size_t)S * S + (size_t)i * S;
    const float* Sr = g_S4 + 1 * (size_t)S * S + (size_t)i * S;
    const float* Sg = g_S4 + 2 * (size_t)S * S + (size_t)i * S;
    const float* Sp = g_S4 + 3 * (size_t)S * S + (size_t)i * S;

    float lcdf[16], rcdf[16];

    {  // left boundary (uses only j <= i)
        float e[16];
        float m = -1e30f;
        float lsum = 0.0f;
        if (j0 <= i) {
#pragma unroll
            for (int u4 = 0; u4 < 4; u4++) {
                float4 v = __ldcs(reinterpret_cast<const float4*>(Sl + j0 + 4 * u4));
                e[4 * u4 + 0] = v.x; e[4 * u4 + 1] = v.y;
                e[4 * u4 + 2] = v.z; e[4 * u4 + 3] = v.w;
            }
#pragma unroll
            for (int u = 0; u < 16; u++) {
                int j = j0 + u;
                float s = (j <= i) ? e[u] * inv_norm : -1e30f;
                e[u] = s;
                m = fmaxf(m, s);
            }
        } else {
#pragma unroll
            for (int u = 0; u < 16; u++) e[u] = -1e30f;
        }
        m = blockMax8(m, sw, w, l);
        if (j0 <= i) {
#pragma unroll
            for (int u = 0; u < 16; u++) {
                int j = j0 + u;
                float ev = (j <= i) ? __expf(e[u] - m) : 0.0f;
                e[u] = ev;
                lsum += ev;
            }
        } else {
#pragma unroll
            for (int u = 0; u < 16; u++) e[u] = 0.0f;
        }
        float tot;
        float off = blockScanExcl(lsum, sw, w, l, &tot);
        float inv = 1.0f / tot;
        float c = 0.0f;
#pragma unroll
        for (int u = 0; u < 16; u++) {
            c += e[u];
            lcdf[u] = (c + off) * inv;
        }
    }

    {  // right boundary (uses only j >= i)
        float e[16];
        float m = -1e30f;
        float rsum = 0.0f;
        if (j0 + 15 >= i) {
#pragma unroll
            for (int u4 = 0; u4 < 4; u4++) {
                float4 v = __ldcs(reinterpret_cast<const float4*>(Sr + j0 + 4 * u4));
                e[4 * u4 + 0] = v.x; e[4 * u4 + 1] = v.y;
                e[4 * u4 + 2] = v.z; e[4 * u4 + 3] = v.w;
            }
#pragma unroll
            for (int u = 0; u < 16; u++) {
                int j = j0 + u;
                float s = (j >= i) ? e[u] * inv_norm : -1e30f;
                e[u] = s;
                m = fmaxf(m, s);
            }
        } else {
#pragma unroll
            for (int u = 0; u < 16; u++) e[u] = -1e30f;
        }
        m = blockMax8(m, sw, w, l);
        if (j0 + 15 >= i) {
#pragma unroll
            for (int u = 0; u < 16; u++) {
                int j = j0 + u;
                float ev = (j >= i) ? __expf(e[u] - m) : 0.0f;
                e[u] = ev;
                rsum += ev;
            }
        } else {
#pragma unroll
            for (int u = 0; u < 16; u++) e[u] = 0.0f;
        }
        float tot;
        float excl = blockScanExcl(rsum, sw, w, l, &tot);
        float suff = tot - excl - rsum;
        float inv = 1.0f / tot;
        float c = 0.0f;
#pragma unroll
        for (int u = 15; u >= 0; u--) {
            c += e[u];
            rcdf[u] = (c + suff) * inv;
        }
    }

    {  // combine + final softmax
        float wv[16], p[16];
#pragma unroll
        for (int u4 = 0; u4 < 4; u4++) {
            float4 vg = __ldcs(reinterpret_cast<const float4*>(Sg + j0 + 4 * u4));
            float4 vp = __ldcs(reinterpret_cast<const float4*>(Sp + j0 + 4 * u4));
            wv[4 * u4 + 0] = vg.x; wv[4 * u4 + 1] = vg.y;
            wv[4 * u4 + 2] = vg.z; wv[4 * u4 + 3] = vg.w;
            p[4 * u4 + 0] = vp.x; p[4 * u4 + 1] = vp.y;
            p[4 * u4 + 2] = vp.z; p[4 * u4 + 3] = vp.w;
        }
        float m = -1e30f;
#pragma unroll
        for (int u = 0; u < 16; u++) {
            float sc = (wv[u] + p[u] * lcdf[u] * rcdf[u]) * inv_norm;
            wv[u] = sc;
            m = fmaxf(m, sc);
        }
        m = blockMax8(m, sw, w, l);
        float lsum = 0.0f;
#pragma unroll
        for (int u = 0; u < 16; u++) {
            float ev = __expf(wv[u] - m);
            wv[u] = ev;
            lsum += ev;
        }
        float tot = blockSum8(lsum, sw, w, l);
        float inv = 1.0f / tot;
        float* Wrow = Wout + (size_t)i * S + j0;
        __half* Hrow = g_Wh + (size_t)i * S + j0;
#pragma unroll
        for (int u4 = 0; u4 < 4; u4++) {
            float4 o;
            o.x = wv[4 * u4 + 0] * inv;
            o.y = wv[4 * u4 + 1] * inv;
            o.z = wv[4 * u4 + 2] * inv;
            o.w = wv[4 * u4 + 3] * inv;
            *reinterpret_cast<float4*>(Wrow + 4 * u4) = o;
            __half2 h01, h23;
            h01.x = __float2half_rn(o.x); h01.y = __float2half_rn(o.y);
            h23.x = __float2half_rn(o.z); h23.y = __float2half_rn(o.w);
            *(__half2*)(Hrow + 4 * u4 + 0) = h01;
            *(__half2*)(Hrow + 4 * u4 + 2) = h23;
        }
    }
}

// ---------------------------------------------------------------------------
// Launch. inputs: x, w_ql, w_kl, w_qr, w_kr, w_qg, w_kg, w_qloc, w_kloc, w_v
// Output layout: [att_output (S*D) | att_weight (S*S)]
// ---------------------------------------------------------------------------
extern "C" void kernel_launch(void* const* d_in, const int* in_sizes, int n_in,
                              void* d_out, int out_size) {
    const float* x = (const float*)d_in[0];
    W9 w9;
    for (int i = 0; i < 9; i++) w9.p[i] = (const float*)d_in[1 + i];

    float* out = (float*)d_out;
    float* Wout = out + SD;

    __nv_bfloat16 *Xh, *Xl, *WTc_h, *WTc_l, *WTv_h, *WTv_l;
    __half *Pc, *VT, *Wh;
    float* S4;
    cudaGetSymbolAddress((void**)&Xh, g_Xh);
    cudaGetSymbolAddress((void**)&Xl, g_Xl);
    cudaGetSymbolAddress((void**)&WTc_h, g_WTc_h);
    cudaGetSymbolAddress((void**)&WTc_l, g_WTc_l);
    cudaGetSymbolAddress((void**)&WTv_h, g_WTv_h);
    cudaGetSymbolAddress((void**)&WTv_l, g_WTv_l);
    cudaGetSymbolAddress((void**)&Pc, g_Pc);
    cudaGetSymbolAddress((void**)&VT, g_VT);
    cudaGetSymbolAddress((void**)&S4, g_S4);
    cudaGetSymbolAddress((void**)&Wh, g_Wh);

    cudaFuncSetAttribute(gemm3_bf16<MODE_SPLIT>,
                         cudaFuncAttributeMaxDynamicSharedMemorySize, SMEM3_SZ);
    cudaFuncSetAttribute(gemm3_bf16<MODE_SPLIT_T>,
                         cudaFuncAttributeMaxDynamicSharedMemorySize, SMEM3_SZ);
    cudaFuncSetAttribute(gemm1_f16,
                         cudaFuncAttributeMaxDynamicSharedMemorySize, SMEM1_SZ);

    // 1) splits
    split_x<<<SD / 256, 256>>>(x, Xh, Xl);
    dim3 tb(32, 8);
    dim3 tg(D / 32, D / 32, 9);
    splitT_all<<<tg, tb>>>(w9, WTc_h, WTc_l, WTv_h, WTv_l);

    // 2) projections (bf16x3 -> single fp16 plane)
    dim3 gp(PCN / 64, S / 64, 1);
    gemm3_bf16<MODE_SPLIT><<<gp, 128, SMEM3_SZ>>>(
        Xh, Xl, WTc_h, WTc_l, Pc, S, PCN, D, D, D);

    dim3 gv(D / 64, S / 64, 1);
    gemm3_bf16<MODE_SPLIT_T><<<gv, 128, SMEM3_SZ>>>(
        Xh, Xl, WTv_h, WTv_l, VT, S, D, D, D, D);

    // 3) four S x S score matrices, single-pass fp16, one batched launch;
    //    z=0 (Sl) lower-triangle blocks only, z=1 (Sr) upper-triangle only.
    dim3 gs(S / 64, S / 64, 4);
    gemm1_f16<<<gs, 128, SMEM1_SZ>>>(
        Pc, Pc + 512, S4, S, S, D, PCN, PCN, 1024, 1024, (long long)S * S, 1);

    // 4) fused boundary softmaxes + cumsums + combine + final softmax
    row_fused<<<S, 256>>>(Wout);

    // 5) att_output = att_weight @ v  (single-pass fp16)
    dim3 gf(D / 64, S / 64, 1);
    gemm1_f16<<<gf, 128, SMEM1_SZ>>>(
        Wh, VT, out, S, D, S, S, S, 0, 0, 0, 0);
}